// round 2
// baseline (speedup 1.0000x reference)
#include <cuda_runtime.h>
#include <math.h>

#define N_NODES 100000
#define N_EDGES 1600000
#define N_CLS   40

// ---------------- scratch (static device allocations; no cudaMalloc) --------
__device__ float g_t[(size_t)N_NODES * 128];   // transform output  (x @ W)
__device__ float g_x[(size_t)N_NODES * 128];   // layer activation buffer
__device__ int   g_deg[N_NODES];
__device__ float g_dis[N_NODES];               // deg^{-1/2} (with self-loop)

// ---------------- degree / normalization ------------------------------------
__global__ void zero_deg_kernel() {
    int i = blockIdx.x * blockDim.x + threadIdx.x;
    if (i < N_NODES) g_deg[i] = 0;
}

__global__ void hist_deg_kernel(const int* __restrict__ ei) {
    int e = blockIdx.x * blockDim.x + threadIdx.x;
    if (e < N_EDGES) {
        int d = ei[N_EDGES + e];
        atomicAdd(&g_deg[d], 1);
    }
}

__global__ void calc_dis_kernel() {
    int i = blockIdx.x * blockDim.x + threadIdx.x;
    if (i < N_NODES) g_dis[i] = rsqrtf((float)(g_deg[i] + 1));
}

// ---------------- GEMM: C[M x Ncols] = A[M x 128] @ W[128 x Ncols] ----------
// 128x128 block tile, 256 threads, 8x8 per thread, BK=16, fp32.
__global__ __launch_bounds__(256) void gemm_kernel(
    const float* __restrict__ A, const float* __restrict__ W,
    float* __restrict__ C, int M, int Ncols)
{
    __shared__ float As[16][128];   // transposed A tile: As[k][row]
    __shared__ float Bs[16][128];   // Bs[k][col]

    const int tid = threadIdx.x;
    const int tx  = tid & 15;       // col group
    const int ty  = tid >> 4;       // row group
    const int rowBase = blockIdx.x * 128;

    float acc[8][8];
#pragma unroll
    for (int i = 0; i < 8; i++)
#pragma unroll
        for (int j = 0; j < 8; j++) acc[i][j] = 0.f;

    for (int k0 = 0; k0 < 128; k0 += 16) {
        // Load A tile (128 rows x 16 k) as 512 float4, 2 per thread.
#pragma unroll
        for (int i = 0; i < 2; i++) {
            int f  = tid + i * 256;
            int r  = f >> 2;
            int kq = f & 3;
            int grow = rowBase + r;
            float4 v = make_float4(0.f, 0.f, 0.f, 0.f);
            if (grow < M)
                v = *(const float4*)&A[(size_t)grow * 128 + k0 + kq * 4];
            As[kq * 4 + 0][r] = v.x;
            As[kq * 4 + 1][r] = v.y;
            As[kq * 4 + 2][r] = v.z;
            As[kq * 4 + 3][r] = v.w;
        }
        // Load B tile (16 k x 128 cols) as 512 float4, 2 per thread.
#pragma unroll
        for (int i = 0; i < 2; i++) {
            int f  = tid + i * 256;
            int k  = f >> 5;
            int cq = f & 31;
            float4 v = make_float4(0.f, 0.f, 0.f, 0.f);
            if (cq * 4 < Ncols)   // Ncols is a multiple of 4 (128 or 40)
                v = *(const float4*)&W[(size_t)(k0 + k) * Ncols + cq * 4];
            *(float4*)&Bs[k][cq * 4] = v;
        }
        __syncthreads();

#pragma unroll
        for (int kk = 0; kk < 16; kk++) {
            float a[8], b[8];
            *(float4*)&a[0] = *(const float4*)&As[kk][ty * 8];
            *(float4*)&a[4] = *(const float4*)&As[kk][ty * 8 + 4];
            *(float4*)&b[0] = *(const float4*)&Bs[kk][tx * 8];
            *(float4*)&b[4] = *(const float4*)&Bs[kk][tx * 8 + 4];
#pragma unroll
            for (int i = 0; i < 8; i++)
#pragma unroll
                for (int j = 0; j < 8; j++)
                    acc[i][j] = fmaf(a[i], b[j], acc[i][j]);
        }
        __syncthreads();
    }

#pragma unroll
    for (int i = 0; i < 8; i++) {
        int r = rowBase + ty * 8 + i;
        if (r >= M) continue;
#pragma unroll
        for (int j = 0; j < 8; j++) {
            int c = tx * 8 + j;
            if (c < Ncols) C[(size_t)r * Ncols + c] = acc[i][j];
        }
    }
}

// ---------------- aggregation (atomic scatter version) ----------------------
// out[i][f] starts as h[i][f]*dis[i]  (self-loop term, pre-scaled);
// edges add h[s][f]*dis[s]; finalize multiplies by dis[i], adds bias, relu.

__global__ void agg_init_kernel(const float* __restrict__ h,
                                float* __restrict__ out, int F) {
    int node = blockIdx.x;
    int f = threadIdx.x;
    if (f < F) {
        size_t idx = (size_t)node * F + f;
        out[idx] = h[idx] * g_dis[node];
    }
}

__global__ void agg_edges_kernel(const float* __restrict__ h,
                                 float* __restrict__ out,
                                 const int* __restrict__ ei, int F) {
    int e = blockIdx.x * blockDim.y + threadIdx.y;
    if (e >= N_EDGES) return;
    int f = threadIdx.x;
    int s = ei[e];
    int d = ei[N_EDGES + e];
    if (f < F) {
        float v = h[(size_t)s * F + f] * g_dis[s];
        atomicAdd(&out[(size_t)d * F + f], v);
    }
}

__global__ void agg_fin_kernel(float* __restrict__ out,
                               const float* __restrict__ bias,
                               int F, int do_relu) {
    int node = blockIdx.x;
    int f = threadIdx.x;
    if (f >= F) return;
    size_t idx = (size_t)node * F + f;
    float v = out[idx] * g_dis[node] + bias[f];
    if (do_relu) v = fmaxf(v, 0.f);
    out[idx] = v;
}

// ---------------- log-softmax over rows of 40 --------------------------------
__global__ void log_softmax_kernel(float* __restrict__ out) {
    int gwarp = (blockIdx.x * blockDim.x + threadIdx.x) >> 5;
    int lane  = threadIdx.x & 31;
    if (gwarp >= N_NODES) return;
    float* row = out + (size_t)gwarp * N_CLS;

    float a = row[lane];
    float b = (lane < N_CLS - 32) ? row[32 + lane] : -INFINITY;

    float m = fmaxf(a, b);
#pragma unroll
    for (int off = 16; off > 0; off >>= 1)
        m = fmaxf(m, __shfl_xor_sync(0xFFFFFFFFu, m, off));

    float s = expf(a - m) + ((lane < N_CLS - 32) ? expf(b - m) : 0.f);
#pragma unroll
    for (int off = 16; off > 0; off >>= 1)
        s += __shfl_xor_sync(0xFFFFFFFFu, s, off);

    float lse = m + logf(s);
    row[lane] = a - lse;
    if (lane < N_CLS - 32) row[32 + lane] = b - lse;
}

// ---------------- launch ------------------------------------------------------
extern "C" void kernel_launch(void* const* d_in, const int* in_sizes, int n_in,
                              void* d_out, int out_size) {
    const float* x  = (const float*)d_in[0];
    const int*   ei = (const int*)d_in[1];      // int32! jax silently downgrades int64
    const float* W1 = (const float*)d_in[2];
    const float* b1 = (const float*)d_in[3];
    const float* W2 = (const float*)d_in[4];
    const float* b2 = (const float*)d_in[5];
    const float* W3 = (const float*)d_in[6];
    const float* b3 = (const float*)d_in[7];
    float* out = (float*)d_out;

    float *t_ptr, *x_ptr;
    cudaGetSymbolAddress((void**)&t_ptr, g_t);
    cudaGetSymbolAddress((void**)&x_ptr, g_x);

    // ---- degree + normalization ----
    zero_deg_kernel<<<(N_NODES + 255) / 256, 256>>>();
    hist_deg_kernel<<<(N_EDGES + 255) / 256, 256>>>(ei);
    calc_dis_kernel<<<(N_NODES + 255) / 256, 256>>>();

    const int gemmGrid = (N_NODES + 127) / 128;

    // ---- layer 1: h = x@W1 ; aggregate ; +b1 ; relu ----
    gemm_kernel<<<gemmGrid, 256>>>(x, W1, t_ptr, N_NODES, 128);
    agg_init_kernel<<<N_NODES, 128>>>(t_ptr, x_ptr, 128);
    {
        dim3 blk(128, 2);
        agg_edges_kernel<<<(N_EDGES + 1) / 2, blk>>>(t_ptr, x_ptr, ei, 128);
    }
    agg_fin_kernel<<<N_NODES, 128>>>(x_ptr, b1, 128, 1);

    // ---- layer 2 ----
    gemm_kernel<<<gemmGrid, 256>>>(x_ptr, W2, t_ptr, N_NODES, 128);
    agg_init_kernel<<<N_NODES, 128>>>(t_ptr, x_ptr, 128);
    {
        dim3 blk(128, 2);
        agg_edges_kernel<<<(N_EDGES + 1) / 2, blk>>>(t_ptr, x_ptr, ei, 128);
    }
    agg_fin_kernel<<<N_NODES, 128>>>(x_ptr, b2, 128, 1);

    // ---- layer 3 (40 cols), aggregate directly into d_out ----
    gemm_kernel<<<gemmGrid, 256>>>(x_ptr, W3, t_ptr, N_NODES, N_CLS);
    agg_init_kernel<<<N_NODES, 64>>>(t_ptr, out, N_CLS);
    {
        dim3 blk(64, 4);
        agg_edges_kernel<<<(N_EDGES + 3) / 4, blk>>>(t_ptr, out, ei, N_CLS);
    }
    agg_fin_kernel<<<N_NODES, 64>>>(out, b3, N_CLS, 0);

    // ---- log-softmax in place ----
    log_softmax_kernel<<<(N_NODES * 32 + 255) / 256, 256>>>(out);
}

// round 3
// speedup vs baseline: 2.7625x; 2.7625x over previous
#include <cuda_runtime.h>
#include <math.h>

#define N_NODES 100000
#define N_EDGES 1600000
#define N_CLS   40

// ---------------- scratch (static device arrays; no cudaMalloc) -------------
__device__ float g_t[(size_t)N_NODES * 128];    // transform output (x @ W)
__device__ float g_x[(size_t)N_NODES * 128];    // layer activation buffer
__device__ int   g_deg[N_NODES];
__device__ float g_dis[N_NODES];                // (deg+1)^{-1/2}
__device__ int   g_rowptr[N_NODES + 1];
__device__ int   g_cursor[N_NODES];
__device__ int   g_csrc[N_EDGES];               // CSR: src ids grouped by dst

// ---------------- degree histogram ------------------------------------------
__global__ void zero_deg_kernel() {
    int i = blockIdx.x * blockDim.x + threadIdx.x;
    if (i < N_NODES) g_deg[i] = 0;
}

__global__ void hist_deg_kernel(const int* __restrict__ ei) {
    int e = blockIdx.x * blockDim.x + threadIdx.x;
    if (e < N_EDGES) atomicAdd(&g_deg[ei[N_EDGES + e]], 1);
}

// ---------------- single-block scan: rowptr, cursor, dis ---------------------
__global__ __launch_bounds__(1024) void scan_kernel() {
    const int T = 1024;
    int tid = threadIdx.x;
    const int per = (N_NODES + T - 1) / T;          // 98
    int start = tid * per;
    int end   = start + per; if (end > N_NODES) end = N_NODES;
    if (start > N_NODES) start = N_NODES;

    int sum = 0;
    for (int i = start; i < end; i++) sum += g_deg[i];

    __shared__ int s[T];
    s[tid] = sum;
    __syncthreads();
    for (int off = 1; off < T; off <<= 1) {
        int v = 0;
        if (tid >= off) v = s[tid - off];
        __syncthreads();
        if (tid >= off) s[tid] += v;
        __syncthreads();
    }
    int run = s[tid] - sum;     // exclusive prefix

    for (int i = start; i < end; i++) {
        int d = g_deg[i];
        g_rowptr[i] = run;
        g_cursor[i] = run;
        g_dis[i] = rsqrtf((float)(d + 1));
        run += d;
    }
    if (end == N_NODES) g_rowptr[N_NODES] = run;
}

__global__ void csr_fill_kernel(const int* __restrict__ ei) {
    int e = blockIdx.x * blockDim.x + threadIdx.x;
    if (e < N_EDGES) {
        int s = ei[e];
        int d = ei[N_EDGES + e];
        int pos = atomicAdd(&g_cursor[d], 1);
        g_csrc[pos] = s;
    }
}

// ---------------- GEMM: C[M x Ncols] = A[M x 128] @ W[128 x Ncols] ----------
__global__ __launch_bounds__(256) void gemm_kernel(
    const float* __restrict__ A, const float* __restrict__ W,
    float* __restrict__ C, int M, int Ncols)
{
    __shared__ float As[16][128];
    __shared__ float Bs[16][128];

    const int tid = threadIdx.x;
    const int tx  = tid & 15;
    const int ty  = tid >> 4;
    const int rowBase = blockIdx.x * 128;

    float acc[8][8];
#pragma unroll
    for (int i = 0; i < 8; i++)
#pragma unroll
        for (int j = 0; j < 8; j++) acc[i][j] = 0.f;

    for (int k0 = 0; k0 < 128; k0 += 16) {
#pragma unroll
        for (int i = 0; i < 2; i++) {
            int f  = tid + i * 256;
            int r  = f >> 2;
            int kq = f & 3;
            int grow = rowBase + r;
            float4 v = make_float4(0.f, 0.f, 0.f, 0.f);
            if (grow < M)
                v = *(const float4*)&A[(size_t)grow * 128 + k0 + kq * 4];
            As[kq * 4 + 0][r] = v.x;
            As[kq * 4 + 1][r] = v.y;
            As[kq * 4 + 2][r] = v.z;
            As[kq * 4 + 3][r] = v.w;
        }
#pragma unroll
        for (int i = 0; i < 2; i++) {
            int f  = tid + i * 256;
            int k  = f >> 5;
            int cq = f & 31;
            float4 v = make_float4(0.f, 0.f, 0.f, 0.f);
            if (cq * 4 < Ncols)
                v = *(const float4*)&W[(size_t)(k0 + k) * Ncols + cq * 4];
            *(float4*)&Bs[k][cq * 4] = v;
        }
        __syncthreads();

#pragma unroll
        for (int kk = 0; kk < 16; kk++) {
            float a[8], b[8];
            *(float4*)&a[0] = *(const float4*)&As[kk][ty * 8];
            *(float4*)&a[4] = *(const float4*)&As[kk][ty * 8 + 4];
            *(float4*)&b[0] = *(const float4*)&Bs[kk][tx * 8];
            *(float4*)&b[4] = *(const float4*)&Bs[kk][tx * 8 + 4];
#pragma unroll
            for (int i = 0; i < 8; i++)
#pragma unroll
                for (int j = 0; j < 8; j++)
                    acc[i][j] = fmaf(a[i], b[j], acc[i][j]);
        }
        __syncthreads();
    }

#pragma unroll
    for (int i = 0; i < 8; i++) {
        int r = rowBase + ty * 8 + i;
        if (r >= M) continue;
#pragma unroll
        for (int j = 0; j < 8; j++) {
            int c = tx * 8 + j;
            if (c < Ncols) C[(size_t)r * Ncols + c] = acc[i][j];
        }
    }
}

// ---------------- fused CSR gather for F=128 ---------------------------------
// out[d] = relu( dis[d] * ( h[d]*dis[d] + sum_{s in N(d)} h[s]*dis[s] ) + b )
__global__ __launch_bounds__(256) void gather128_kernel(
    const float* __restrict__ h, float* __restrict__ out,
    const float* __restrict__ bias, int do_relu)
{
    int warp = threadIdx.x >> 5;
    int lane = threadIdx.x & 31;
    int node = blockIdx.x * 8 + warp;
    if (node >= N_NODES) return;

    float dd = g_dis[node];
    float4 acc0 = *(const float4*)&h[(size_t)node * 128 + lane * 4];
    acc0.x *= dd; acc0.y *= dd; acc0.z *= dd; acc0.w *= dd;
    float4 acc1 = make_float4(0.f, 0.f, 0.f, 0.f);

    int e   = g_rowptr[node];
    int end = g_rowptr[node + 1];
    for (; e + 1 < end; e += 2) {
        int s0 = g_csrc[e];
        int s1 = g_csrc[e + 1];
        float d0 = g_dis[s0];
        float d1 = g_dis[s1];
        float4 v0 = *(const float4*)&h[(size_t)s0 * 128 + lane * 4];
        float4 v1 = *(const float4*)&h[(size_t)s1 * 128 + lane * 4];
        acc0.x += v0.x * d0; acc0.y += v0.y * d0; acc0.z += v0.z * d0; acc0.w += v0.w * d0;
        acc1.x += v1.x * d1; acc1.y += v1.y * d1; acc1.z += v1.z * d1; acc1.w += v1.w * d1;
    }
    if (e < end) {
        int s0 = g_csrc[e];
        float d0 = g_dis[s0];
        float4 v0 = *(const float4*)&h[(size_t)s0 * 128 + lane * 4];
        acc0.x += v0.x * d0; acc0.y += v0.y * d0; acc0.z += v0.z * d0; acc0.w += v0.w * d0;
    }

    float4 b = *(const float4*)&bias[lane * 4];
    float4 r;
    r.x = (acc0.x + acc1.x) * dd + b.x;
    r.y = (acc0.y + acc1.y) * dd + b.y;
    r.z = (acc0.z + acc1.z) * dd + b.z;
    r.w = (acc0.w + acc1.w) * dd + b.w;
    if (do_relu) {
        r.x = fmaxf(r.x, 0.f); r.y = fmaxf(r.y, 0.f);
        r.z = fmaxf(r.z, 0.f); r.w = fmaxf(r.w, 0.f);
    }
    *(float4*)&out[(size_t)node * 128 + lane * 4] = r;
}

// ---------------- fused CSR gather (F=40) + bias + log-softmax ---------------
__global__ __launch_bounds__(256) void gather40_softmax_kernel(
    const float* __restrict__ h, const float* __restrict__ bias,
    float* __restrict__ out)
{
    int warp = threadIdx.x >> 5;
    int lane = threadIdx.x & 31;
    int node = blockIdx.x * 8 + warp;
    if (node >= N_NODES) return;

    float dd = g_dis[node];
    const float* hr = h + (size_t)node * N_CLS;
    float accA = hr[lane] * dd;                                  // f = lane
    float accB = (lane < 8) ? hr[32 + lane] * dd : 0.f;          // f = 32+lane

    int e   = g_rowptr[node];
    int end = g_rowptr[node + 1];
    for (; e < end; e++) {
        int s = g_csrc[e];
        float ds = g_dis[s];
        const float* hs = h + (size_t)s * N_CLS;
        accA += hs[lane] * ds;
        if (lane < 8) accB += hs[32 + lane] * ds;
    }

    float a = accA * dd + bias[lane];
    float b = (lane < 8) ? (accB * dd + bias[32 + lane]) : -INFINITY;

    float m = fmaxf(a, b);
#pragma unroll
    for (int off = 16; off > 0; off >>= 1)
        m = fmaxf(m, __shfl_xor_sync(0xFFFFFFFFu, m, off));

    float s = expf(a - m) + ((lane < 8) ? expf(b - m) : 0.f);
#pragma unroll
    for (int off = 16; off > 0; off >>= 1)
        s += __shfl_xor_sync(0xFFFFFFFFu, s, off);

    float lse = m + logf(s);
    out[(size_t)node * N_CLS + lane] = a - lse;
    if (lane < 8) out[(size_t)node * N_CLS + 32 + lane] = b - lse;
}

// ---------------- launch ------------------------------------------------------
extern "C" void kernel_launch(void* const* d_in, const int* in_sizes, int n_in,
                              void* d_out, int out_size) {
    const float* x  = (const float*)d_in[0];
    const int*   ei = (const int*)d_in[1];      // int32 [2][N_EDGES]
    const float* W1 = (const float*)d_in[2];
    const float* b1 = (const float*)d_in[3];
    const float* W2 = (const float*)d_in[4];
    const float* b2 = (const float*)d_in[5];
    const float* W3 = (const float*)d_in[6];
    const float* b3 = (const float*)d_in[7];
    float* out = (float*)d_out;

    float *t_ptr, *x_ptr;
    cudaGetSymbolAddress((void**)&t_ptr, g_t);
    cudaGetSymbolAddress((void**)&x_ptr, g_x);

    // ---- CSR build + normalization ----
    zero_deg_kernel<<<(N_NODES + 255) / 256, 256>>>();
    hist_deg_kernel<<<(N_EDGES + 255) / 256, 256>>>(ei);
    scan_kernel<<<1, 1024>>>();
    csr_fill_kernel<<<(N_EDGES + 255) / 256, 256>>>(ei);

    const int gemmGrid   = (N_NODES + 127) / 128;
    const int gatherGrid = (N_NODES + 7) / 8;

    // ---- layer 1 ----
    gemm_kernel<<<gemmGrid, 256>>>(x, W1, t_ptr, N_NODES, 128);
    gather128_kernel<<<gatherGrid, 256>>>(t_ptr, x_ptr, b1, 1);

    // ---- layer 2 ----
    gemm_kernel<<<gemmGrid, 256>>>(x_ptr, W2, t_ptr, N_NODES, 128);
    gather128_kernel<<<gatherGrid, 256>>>(t_ptr, x_ptr, b2, 1);

    // ---- layer 3 (40 cols) + fused log-softmax ----
    gemm_kernel<<<gemmGrid, 256>>>(x_ptr, W3, t_ptr, N_NODES, N_CLS);
    gather40_softmax_kernel<<<gatherGrid, 256>>>(t_ptr, b3, out);
}

// round 6
// speedup vs baseline: 3.0931x; 1.1197x over previous
#include <cuda_runtime.h>
#include <stdint.h>
#include <math.h>

#define N_NODES 100000
#define N_EDGES 1600000
#define N_CLS   40

// ---------------- scratch (static device arrays; no cudaMalloc) -------------
__device__ float g_t[(size_t)N_NODES * 128];    // transform output (x @ W)
__device__ float g_x[(size_t)N_NODES * 128];    // layer activation buffer
__device__ int   g_deg[N_NODES];
__device__ float g_dis[N_NODES];                // (deg+1)^{-1/2}
__device__ int   g_rowptr[N_NODES + 1];
__device__ int   g_cursor[N_NODES];
__device__ int   g_csrc[N_EDGES];               // CSR: src ids grouped by dst

// ---------------- degree histogram ------------------------------------------
__global__ void zero_deg_kernel() {
    int i = blockIdx.x * blockDim.x + threadIdx.x;
    if (i < N_NODES) g_deg[i] = 0;
}

__global__ void hist_deg_kernel(const int* __restrict__ ei) {
    int e = blockIdx.x * blockDim.x + threadIdx.x;
    if (e < N_EDGES) atomicAdd(&g_deg[ei[N_EDGES + e]], 1);
}

// ---------------- single-block scan: rowptr, cursor, dis ---------------------
__global__ __launch_bounds__(1024) void scan_kernel() {
    const int T = 1024;
    int tid = threadIdx.x;
    const int per = (N_NODES + T - 1) / T;          // 98
    int start = tid * per;
    int end   = start + per; if (end > N_NODES) end = N_NODES;
    if (start > N_NODES) start = N_NODES;

    int sum = 0;
    for (int i = start; i < end; i++) sum += g_deg[i];

    __shared__ int s[T];
    s[tid] = sum;
    __syncthreads();
    for (int off = 1; off < T; off <<= 1) {
        int v = 0;
        if (tid >= off) v = s[tid - off];
        __syncthreads();
        if (tid >= off) s[tid] += v;
        __syncthreads();
    }
    int run = s[tid] - sum;     // exclusive prefix

    for (int i = start; i < end; i++) {
        int d = g_deg[i];
        g_rowptr[i] = run;
        g_cursor[i] = run;
        g_dis[i] = rsqrtf((float)(d + 1));
        run += d;
    }
    if (end == N_NODES) g_rowptr[N_NODES] = run;
}

__global__ void csr_fill_kernel(const int* __restrict__ ei) {
    int e = blockIdx.x * blockDim.x + threadIdx.x;
    if (e < N_EDGES) {
        int s = ei[e];
        int d = ei[N_EDGES + e];
        int pos = atomicAdd(&g_cursor[d], 1);
        g_csrc[pos] = s;
    }
}

// ---------------- helpers ----------------------------------------------------
// tf32 destination must be a .b32 register per PTX spec.
__device__ __forceinline__ uint32_t tf32_bits(float x) {
    uint32_t r;
    asm("cvt.rna.tf32.f32 %0, %1;" : "=r"(r) : "f"(x));
    return r;
}

// returns hi (tf32-rounded, as float view) and lo (tf32 of residual, float view)
__device__ __forceinline__ void tf32_split(float x, float& hi, float& lo) {
    uint32_t hb = tf32_bits(x);
    float h = __uint_as_float(hb);
    uint32_t lb = tf32_bits(x - h);
    hi = h;
    lo = __uint_as_float(lb);
}

__device__ __forceinline__ void mma_tf32(float* c, uint32_t a0, uint32_t a1,
                                         uint32_t a2, uint32_t a3,
                                         uint32_t b0, uint32_t b1) {
    asm volatile(
        "mma.sync.aligned.m16n8k8.row.col.f32.tf32.tf32.f32 "
        "{%0,%1,%2,%3}, {%4,%5,%6,%7}, {%8,%9}, {%0,%1,%2,%3};"
        : "+f"(c[0]), "+f"(c[1]), "+f"(c[2]), "+f"(c[3])
        : "r"(a0), "r"(a1), "r"(a2), "r"(a3), "r"(b0), "r"(b1));
}

// ---------------- 3xTF32 tensor-core GEMM ------------------------------------
// C[M x Ncols] = A[M x 128] @ W[128 x Ncols].  Block tile 128x128, BK=16.
// 8 warps (2 m x 4 n), warp tile 64x32 via m16n8k8.
__global__ __launch_bounds__(256) void gemm_tf32_kernel(
    const float* __restrict__ A, const float* __restrict__ W,
    float* __restrict__ C, int M, int Ncols)
{
    __shared__ float Ah[128][20];
    __shared__ float Al[128][20];
    __shared__ float Bh[16][132];
    __shared__ float Bl[16][132];

    const int tid  = threadIdx.x;
    const int warp = tid >> 5;
    const int lane = tid & 31;
    const int g    = lane >> 2;          // groupID 0..7
    const int tg   = lane & 3;           // tid-in-group 0..3
    const int wm   = (warp >> 2) * 64;   // warp m offset
    const int wn   = (warp & 3) * 32;    // warp n offset
    const int rowBase = blockIdx.x * 128;

    float acc[4][4][4];
#pragma unroll
    for (int mt = 0; mt < 4; mt++)
#pragma unroll
        for (int nt = 0; nt < 4; nt++)
#pragma unroll
            for (int i = 0; i < 4; i++) acc[mt][nt][i] = 0.f;

    for (int k0 = 0; k0 < 128; k0 += 16) {
        // --- stage A tile (128 x 16) as hi/lo tf32 ---
#pragma unroll
        for (int i = 0; i < 2; i++) {
            int f  = tid + i * 256;
            int r  = f >> 2;
            int kq = f & 3;
            int grow = rowBase + r;
            float4 v = make_float4(0.f, 0.f, 0.f, 0.f);
            if (grow < M)
                v = *(const float4*)&A[(size_t)grow * 128 + k0 + kq * 4];
            float4 h, l;
            tf32_split(v.x, h.x, l.x);
            tf32_split(v.y, h.y, l.y);
            tf32_split(v.z, h.z, l.z);
            tf32_split(v.w, h.w, l.w);
            *(float4*)&Ah[r][kq * 4] = h;
            *(float4*)&Al[r][kq * 4] = l;
        }
        // --- stage B tile (16 x 128) as hi/lo tf32 ---
#pragma unroll
        for (int i = 0; i < 2; i++) {
            int f  = tid + i * 256;
            int k  = f >> 5;
            int cq = f & 31;
            float4 v = make_float4(0.f, 0.f, 0.f, 0.f);
            if (cq * 4 < Ncols)
                v = *(const float4*)&W[(size_t)(k0 + k) * Ncols + cq * 4];
            float4 h, l;
            tf32_split(v.x, h.x, l.x);
            tf32_split(v.y, h.y, l.y);
            tf32_split(v.z, h.z, l.z);
            tf32_split(v.w, h.w, l.w);
            *(float4*)&Bh[k][cq * 4] = h;
            *(float4*)&Bl[k][cq * 4] = l;
        }
        __syncthreads();

#pragma unroll
        for (int kk = 0; kk < 16; kk += 8) {
#pragma unroll
            for (int term = 0; term < 3; term++) {
                const float (*As)[20]  = (term == 1) ? Al : Ah;
                const float (*Bs)[132] = (term == 2) ? Bl : Bh;

                uint32_t af[4][4];
#pragma unroll
                for (int mt = 0; mt < 4; mt++) {
                    int r = wm + mt * 16 + g;
                    af[mt][0] = __float_as_uint(As[r    ][kk + tg    ]);
                    af[mt][1] = __float_as_uint(As[r + 8][kk + tg    ]);
                    af[mt][2] = __float_as_uint(As[r    ][kk + tg + 4]);
                    af[mt][3] = __float_as_uint(As[r + 8][kk + tg + 4]);
                }
                uint32_t bf[4][2];
#pragma unroll
                for (int nt = 0; nt < 4; nt++) {
                    int c = wn + nt * 8 + g;
                    bf[nt][0] = __float_as_uint(Bs[kk + tg    ][c]);
                    bf[nt][1] = __float_as_uint(Bs[kk + tg + 4][c]);
                }
#pragma unroll
                for (int mt = 0; mt < 4; mt++)
#pragma unroll
                    for (int nt = 0; nt < 4; nt++)
                        mma_tf32(acc[mt][nt],
                                 af[mt][0], af[mt][1], af[mt][2], af[mt][3],
                                 bf[nt][0], bf[nt][1]);
            }
        }
        __syncthreads();
    }

    // --- epilogue ---
#pragma unroll
    for (int mt = 0; mt < 4; mt++) {
#pragma unroll
        for (int nt = 0; nt < 4; nt++) {
            int col = wn + nt * 8 + 2 * tg;
            if (col >= Ncols) continue;
            int r0 = rowBase + wm + mt * 16 + g;
            int r1 = r0 + 8;
            if (r0 < M)
                *(float2*)&C[(size_t)r0 * Ncols + col] =
                    make_float2(acc[mt][nt][0], acc[mt][nt][1]);
            if (r1 < M)
                *(float2*)&C[(size_t)r1 * Ncols + col] =
                    make_float2(acc[mt][nt][2], acc[mt][nt][3]);
        }
    }
}

// ---------------- fused CSR gather for F=128 ---------------------------------
// out[d] = relu( dis[d] * ( h[d]*dis[d] + sum_{s in N(d)} h[s]*dis[s] ) + b )
__global__ __launch_bounds__(256) void gather128_kernel(
    const float* __restrict__ h, float* __restrict__ out,
    const float* __restrict__ bias, int do_relu)
{
    int warp = threadIdx.x >> 5;
    int lane = threadIdx.x & 31;
    int node = blockIdx.x * 8 + warp;
    if (node >= N_NODES) return;

    float dd = g_dis[node];
    float4 acc0 = *(const float4*)&h[(size_t)node * 128 + lane * 4];
    acc0.x *= dd; acc0.y *= dd; acc0.z *= dd; acc0.w *= dd;
    float4 acc1 = make_float4(0.f, 0.f, 0.f, 0.f);

    int e   = g_rowptr[node];
    int end = g_rowptr[node + 1];
    for (; e + 1 < end; e += 2) {
        int s0 = g_csrc[e];
        int s1 = g_csrc[e + 1];
        float d0 = g_dis[s0];
        float d1 = g_dis[s1];
        float4 v0 = *(const float4*)&h[(size_t)s0 * 128 + lane * 4];
        float4 v1 = *(const float4*)&h[(size_t)s1 * 128 + lane * 4];
        acc0.x += v0.x * d0; acc0.y += v0.y * d0; acc0.z += v0.z * d0; acc0.w += v0.w * d0;
        acc1.x += v1.x * d1; acc1.y += v1.y * d1; acc1.z += v1.z * d1; acc1.w += v1.w * d1;
    }
    if (e < end) {
        int s0 = g_csrc[e];
        float d0 = g_dis[s0];
        float4 v0 = *(const float4*)&h[(size_t)s0 * 128 + lane * 4];
        acc0.x += v0.x * d0; acc0.y += v0.y * d0; acc0.z += v0.z * d0; acc0.w += v0.w * d0;
    }

    float4 b = *(const float4*)&bias[lane * 4];
    float4 r;
    r.x = (acc0.x + acc1.x) * dd + b.x;
    r.y = (acc0.y + acc1.y) * dd + b.y;
    r.z = (acc0.z + acc1.z) * dd + b.z;
    r.w = (acc0.w + acc1.w) * dd + b.w;
    if (do_relu) {
        r.x = fmaxf(r.x, 0.f); r.y = fmaxf(r.y, 0.f);
        r.z = fmaxf(r.z, 0.f); r.w = fmaxf(r.w, 0.f);
    }
    *(float4*)&out[(size_t)node * 128 + lane * 4] = r;
}

// ---------------- fused CSR gather (F=40) + bias + log-softmax ---------------
__global__ __launch_bounds__(256) void gather40_softmax_kernel(
    const float* __restrict__ h, const float* __restrict__ bias,
    float* __restrict__ out)
{
    int warp = threadIdx.x >> 5;
    int lane = threadIdx.x & 31;
    int node = blockIdx.x * 8 + warp;
    if (node >= N_NODES) return;

    float dd = g_dis[node];
    const float* hr = h + (size_t)node * N_CLS;
    float accA = hr[lane] * dd;                                  // f = lane
    float accB = (lane < 8) ? hr[32 + lane] * dd : 0.f;          // f = 32+lane

    int e   = g_rowptr[node];
    int end = g_rowptr[node + 1];
    for (; e < end; e++) {
        int s = g_csrc[e];
        float ds = g_dis[s];
        const float* hs = h + (size_t)s * N_CLS;
        accA += hs[lane] * ds;
        if (lane < 8) accB += hs[32 + lane] * ds;
    }

    float a = accA * dd + bias[lane];
    float b = (lane < 8) ? (accB * dd + bias[32 + lane]) : -INFINITY;

    float m = fmaxf(a, b);
#pragma unroll
    for (int off = 16; off > 0; off >>= 1)
        m = fmaxf(m, __shfl_xor_sync(0xFFFFFFFFu, m, off));

    float s = expf(a - m) + ((lane < 8) ? expf(b - m) : 0.f);
#pragma unroll
    for (int off = 16; off > 0; off >>= 1)
        s += __shfl_xor_sync(0xFFFFFFFFu, s, off);

    float lse = m + logf(s);
    out[(size_t)node * N_CLS + lane] = a - lse;
    if (lane < 8) out[(size_t)node * N_CLS + 32 + lane] = b - lse;
}

// ---------------- launch ------------------------------------------------------
extern "C" void kernel_launch(void* const* d_in, const int* in_sizes, int n_in,
                              void* d_out, int out_size) {
    const float* x  = (const float*)d_in[0];
    const int*   ei = (const int*)d_in[1];      // int32 [2][N_EDGES]
    const float* W1 = (const float*)d_in[2];
    const float* b1 = (const float*)d_in[3];
    const float* W2 = (const float*)d_in[4];
    const float* b2 = (const float*)d_in[5];
    const float* W3 = (const float*)d_in[6];
    const float* b3 = (const float*)d_in[7];
    float* out = (float*)d_out;

    float *t_ptr, *x_ptr;
    cudaGetSymbolAddress((void**)&t_ptr, g_t);
    cudaGetSymbolAddress((void**)&x_ptr, g_x);

    // ---- CSR build + normalization ----
    zero_deg_kernel<<<(N_NODES + 255) / 256, 256>>>();
    hist_deg_kernel<<<(N_EDGES + 255) / 256, 256>>>(ei);
    scan_kernel<<<1, 1024>>>();
    csr_fill_kernel<<<(N_EDGES + 255) / 256, 256>>>(ei);

    const int gemmGrid   = (N_NODES + 127) / 128;
    const int gatherGrid = (N_NODES + 7) / 8;

    // ---- layer 1 ----
    gemm_tf32_kernel<<<gemmGrid, 256>>>(x, W1, t_ptr, N_NODES, 128);
    gather128_kernel<<<gatherGrid, 256>>>(t_ptr, x_ptr, b1, 1);

    // ---- layer 2 ----
    gemm_tf32_kernel<<<gemmGrid, 256>>>(x_ptr, W2, t_ptr, N_NODES, 128);
    gather128_kernel<<<gatherGrid, 256>>>(t_ptr, x_ptr, b2, 1);

    // ---- layer 3 (40 cols) + fused log-softmax ----
    gemm_tf32_kernel<<<gemmGrid, 256>>>(x_ptr, W3, t_ptr, N_NODES, N_CLS);
    gather40_softmax_kernel<<<gatherGrid, 256>>>(t_ptr, b3, out);
}

// round 7
// speedup vs baseline: 3.3815x; 1.0932x over previous
#include <cuda_runtime.h>
#include <stdint.h>
#include <math.h>

#define N_NODES 100000
#define N_EDGES 1600000
#define N_CLS   40

// ---------------- scratch (static device arrays; no cudaMalloc) -------------
__device__ float g_t[(size_t)N_NODES * 128];    // transform output (x @ W)
__device__ float g_x[(size_t)N_NODES * 128];    // layer activation buffer
__device__ int   g_deg[N_NODES];
__device__ float g_dis[N_NODES];                // (deg+1)^{-1/2}
__device__ int   g_rowptr[N_NODES + 1];
__device__ int   g_cursor[N_NODES];
__device__ int   g_csrc[N_EDGES];               // CSR: src ids grouped by dst

// ---------------- degree histogram ------------------------------------------
__global__ void zero_deg_kernel() {
    int i = blockIdx.x * blockDim.x + threadIdx.x;
    if (i < N_NODES) g_deg[i] = 0;
}

__global__ void hist_deg_kernel(const int* __restrict__ ei) {
    int e = blockIdx.x * blockDim.x + threadIdx.x;
    if (e < N_EDGES) atomicAdd(&g_deg[ei[N_EDGES + e]], 1);
}

// ---------------- single-block scan: rowptr, cursor, dis ---------------------
__global__ __launch_bounds__(1024) void scan_kernel() {
    const int T = 1024;
    int tid = threadIdx.x;
    const int per = (N_NODES + T - 1) / T;          // 98
    int start = tid * per;
    int end   = start + per; if (end > N_NODES) end = N_NODES;
    if (start > N_NODES) start = N_NODES;

    int sum = 0;
    for (int i = start; i < end; i++) sum += g_deg[i];

    __shared__ int s[T];
    s[tid] = sum;
    __syncthreads();
    for (int off = 1; off < T; off <<= 1) {
        int v = 0;
        if (tid >= off) v = s[tid - off];
        __syncthreads();
        if (tid >= off) s[tid] += v;
        __syncthreads();
    }
    int run = s[tid] - sum;     // exclusive prefix

    for (int i = start; i < end; i++) {
        int d = g_deg[i];
        g_rowptr[i] = run;
        g_cursor[i] = run;
        g_dis[i] = rsqrtf((float)(d + 1));
        run += d;
    }
    if (end == N_NODES) g_rowptr[N_NODES] = run;
}

__global__ void csr_fill_kernel(const int* __restrict__ ei) {
    int e = blockIdx.x * blockDim.x + threadIdx.x;
    if (e < N_EDGES) {
        int s = ei[e];
        int d = ei[N_EDGES + e];
        int pos = atomicAdd(&g_cursor[d], 1);
        g_csrc[pos] = s;
    }
}

// ---------------- helpers ----------------------------------------------------
__device__ __forceinline__ uint32_t tf32_bits(float x) {
    uint32_t r;
    asm("cvt.rna.tf32.f32 %0, %1;" : "=r"(r) : "f"(x));
    return r;
}

__device__ __forceinline__ void tf32_split(float x, float& hi, float& lo) {
    uint32_t hb = tf32_bits(x);
    float h = __uint_as_float(hb);
    uint32_t lb = tf32_bits(x - h);
    hi = h;
    lo = __uint_as_float(lb);
}

__device__ __forceinline__ void mma_tf32(float* c, uint32_t a0, uint32_t a1,
                                         uint32_t a2, uint32_t a3,
                                         uint32_t b0, uint32_t b1) {
    asm volatile(
        "mma.sync.aligned.m16n8k8.row.col.f32.tf32.tf32.f32 "
        "{%0,%1,%2,%3}, {%4,%5,%6,%7}, {%8,%9}, {%0,%1,%2,%3};"
        : "+f"(c[0]), "+f"(c[1]), "+f"(c[2]), "+f"(c[3])
        : "r"(a0), "r"(a1), "r"(a2), "r"(a3), "r"(b0), "r"(b1));
}

// ---------------- 3xTF32 tensor-core GEMM ------------------------------------
// C[M x Ncols] = A[M x 128] @ W[128 x Ncols].  Block tile 128x128, BK=16.
// 8 warps (2 m x 4 n), warp tile 64x32 via m16n8k8.
// Fragments hoisted across the 3 precision terms; global loads software-pipelined.
__global__ __launch_bounds__(256) void gemm_tf32_kernel(
    const float* __restrict__ A, const float* __restrict__ W,
    float* __restrict__ C, int M, int Ncols)
{
    __shared__ float Ah[128][20];
    __shared__ float Al[128][20];
    __shared__ float Bh[16][136];
    __shared__ float Bl[16][136];

    const int tid  = threadIdx.x;
    const int warp = tid >> 5;
    const int lane = tid & 31;
    const int g    = lane >> 2;          // groupID 0..7
    const int tg   = lane & 3;           // tid-in-group 0..3
    const int wm   = (warp >> 2) * 64;   // warp m offset
    const int wn   = (warp & 3) * 32;    // warp n offset
    const int rowBase = blockIdx.x * 128;

    // addressing for the staging loads (2 float4 each for A and B per thread)
    const int ar0 = tid >> 2,            akq0 = tid & 3;
    const int ar1 = (tid + 256) >> 2,    akq1 = (tid + 256) & 3;
    const int bk0 = tid >> 5,            bcq0 = tid & 31;
    const int bk1 = (tid + 256) >> 5,    bcq1 = (tid + 256) & 31;

    float acc[4][4][4];
#pragma unroll
    for (int mt = 0; mt < 4; mt++)
#pragma unroll
        for (int nt = 0; nt < 4; nt++)
#pragma unroll
            for (int i = 0; i < 4; i++) acc[mt][nt][i] = 0.f;

    // --- prologue: load tile k0=0 into registers ---
    float4 pa0, pa1, pb0, pb1;
    {
        int grow0 = rowBase + ar0, grow1 = rowBase + ar1;
        pa0 = (grow0 < M) ? *(const float4*)&A[(size_t)grow0 * 128 + akq0 * 4]
                          : make_float4(0.f, 0.f, 0.f, 0.f);
        pa1 = (grow1 < M) ? *(const float4*)&A[(size_t)grow1 * 128 + akq1 * 4]
                          : make_float4(0.f, 0.f, 0.f, 0.f);
        pb0 = (bcq0 * 4 < Ncols) ? *(const float4*)&W[(size_t)bk0 * Ncols + bcq0 * 4]
                                 : make_float4(0.f, 0.f, 0.f, 0.f);
        pb1 = (bcq1 * 4 < Ncols) ? *(const float4*)&W[(size_t)bk1 * Ncols + bcq1 * 4]
                                 : make_float4(0.f, 0.f, 0.f, 0.f);
    }

    for (int k0 = 0; k0 < 128; k0 += 16) {
        // --- store staged registers to smem with hi/lo split ---
        {
            float4 h, l;
            tf32_split(pa0.x, h.x, l.x); tf32_split(pa0.y, h.y, l.y);
            tf32_split(pa0.z, h.z, l.z); tf32_split(pa0.w, h.w, l.w);
            *(float4*)&Ah[ar0][akq0 * 4] = h;
            *(float4*)&Al[ar0][akq0 * 4] = l;
            tf32_split(pa1.x, h.x, l.x); tf32_split(pa1.y, h.y, l.y);
            tf32_split(pa1.z, h.z, l.z); tf32_split(pa1.w, h.w, l.w);
            *(float4*)&Ah[ar1][akq1 * 4] = h;
            *(float4*)&Al[ar1][akq1 * 4] = l;
            tf32_split(pb0.x, h.x, l.x); tf32_split(pb0.y, h.y, l.y);
            tf32_split(pb0.z, h.z, l.z); tf32_split(pb0.w, h.w, l.w);
            *(float4*)&Bh[bk0][bcq0 * 4] = h;
            *(float4*)&Bl[bk0][bcq0 * 4] = l;
            tf32_split(pb1.x, h.x, l.x); tf32_split(pb1.y, h.y, l.y);
            tf32_split(pb1.z, h.z, l.z); tf32_split(pb1.w, h.w, l.w);
            *(float4*)&Bh[bk1][bcq1 * 4] = h;
            *(float4*)&Bl[bk1][bcq1 * 4] = l;
        }
        __syncthreads();

        // --- prefetch next tile's globals (overlaps with mma below) ---
        int kn = k0 + 16;
        if (kn < 128) {
            int grow0 = rowBase + ar0, grow1 = rowBase + ar1;
            pa0 = (grow0 < M) ? *(const float4*)&A[(size_t)grow0 * 128 + kn + akq0 * 4]
                              : make_float4(0.f, 0.f, 0.f, 0.f);
            pa1 = (grow1 < M) ? *(const float4*)&A[(size_t)grow1 * 128 + kn + akq1 * 4]
                              : make_float4(0.f, 0.f, 0.f, 0.f);
            pb0 = (bcq0 * 4 < Ncols) ? *(const float4*)&W[(size_t)(kn + bk0) * Ncols + bcq0 * 4]
                                     : make_float4(0.f, 0.f, 0.f, 0.f);
            pb1 = (bcq1 * 4 < Ncols) ? *(const float4*)&W[(size_t)(kn + bk1) * Ncols + bcq1 * 4]
                                     : make_float4(0.f, 0.f, 0.f, 0.f);
        }

        // --- mma: fragments loaded once, reused for all 3 terms ---
#pragma unroll
        for (int kk = 0; kk < 16; kk += 8) {
            uint32_t bh[4][2], bl[4][2];
#pragma unroll
            for (int nt = 0; nt < 4; nt++) {
                int c = wn + nt * 8 + g;
                bh[nt][0] = __float_as_uint(Bh[kk + tg    ][c]);
                bh[nt][1] = __float_as_uint(Bh[kk + tg + 4][c]);
                bl[nt][0] = __float_as_uint(Bl[kk + tg    ][c]);
                bl[nt][1] = __float_as_uint(Bl[kk + tg + 4][c]);
            }
#pragma unroll
            for (int mt = 0; mt < 4; mt++) {
                int r = wm + mt * 16 + g;
                uint32_t ah0 = __float_as_uint(Ah[r    ][kk + tg    ]);
                uint32_t ah1 = __float_as_uint(Ah[r + 8][kk + tg    ]);
                uint32_t ah2 = __float_as_uint(Ah[r    ][kk + tg + 4]);
                uint32_t ah3 = __float_as_uint(Ah[r + 8][kk + tg + 4]);
                uint32_t al0 = __float_as_uint(Al[r    ][kk + tg    ]);
                uint32_t al1 = __float_as_uint(Al[r + 8][kk + tg    ]);
                uint32_t al2 = __float_as_uint(Al[r    ][kk + tg + 4]);
                uint32_t al3 = __float_as_uint(Al[r + 8][kk + tg + 4]);
#pragma unroll
                for (int nt = 0; nt < 4; nt++)
                    mma_tf32(acc[mt][nt], ah0, ah1, ah2, ah3, bh[nt][0], bh[nt][1]);
#pragma unroll
                for (int nt = 0; nt < 4; nt++)
                    mma_tf32(acc[mt][nt], al0, al1, al2, al3, bh[nt][0], bh[nt][1]);
#pragma unroll
                for (int nt = 0; nt < 4; nt++)
                    mma_tf32(acc[mt][nt], ah0, ah1, ah2, ah3, bl[nt][0], bl[nt][1]);
            }
        }
        __syncthreads();
    }

    // --- epilogue ---
#pragma unroll
    for (int mt = 0; mt < 4; mt++) {
#pragma unroll
        for (int nt = 0; nt < 4; nt++) {
            int col = wn + nt * 8 + 2 * tg;
            if (col >= Ncols) continue;
            int r0 = rowBase + wm + mt * 16 + g;
            int r1 = r0 + 8;
            if (r0 < M)
                *(float2*)&C[(size_t)r0 * Ncols + col] =
                    make_float2(acc[mt][nt][0], acc[mt][nt][1]);
            if (r1 < M)
                *(float2*)&C[(size_t)r1 * Ncols + col] =
                    make_float2(acc[mt][nt][2], acc[mt][nt][3]);
        }
    }
}

// ---------------- fused CSR gather for F=128 ---------------------------------
// out[d] = relu( dis[d] * ( h[d]*dis[d] + sum_{s in N(d)} h[s]*dis[s] ) + b )
__global__ __launch_bounds__(256) void gather128_kernel(
    const float* __restrict__ h, float* __restrict__ out,
    const float* __restrict__ bias, int do_relu)
{
    int warp = threadIdx.x >> 5;
    int lane = threadIdx.x & 31;
    int node = blockIdx.x * 8 + warp;
    if (node >= N_NODES) return;

    float dd = g_dis[node];
    float4 acc0 = *(const float4*)&h[(size_t)node * 128 + lane * 4];
    acc0.x *= dd; acc0.y *= dd; acc0.z *= dd; acc0.w *= dd;
    float4 acc1 = make_float4(0.f, 0.f, 0.f, 0.f);

    int e   = g_rowptr[node];
    int end = g_rowptr[node + 1];

    for (; e + 3 < end; e += 4) {
        int s0 = g_csrc[e];
        int s1 = g_csrc[e + 1];
        int s2 = g_csrc[e + 2];
        int s3 = g_csrc[e + 3];
        float d0 = g_dis[s0], d1 = g_dis[s1], d2 = g_dis[s2], d3 = g_dis[s3];
        float4 v0 = *(const float4*)&h[(size_t)s0 * 128 + lane * 4];
        float4 v1 = *(const float4*)&h[(size_t)s1 * 128 + lane * 4];
        float4 v2 = *(const float4*)&h[(size_t)s2 * 128 + lane * 4];
        float4 v3 = *(const float4*)&h[(size_t)s3 * 128 + lane * 4];
        acc0.x += v0.x * d0; acc0.y += v0.y * d0; acc0.z += v0.z * d0; acc0.w += v0.w * d0;
        acc1.x += v1.x * d1; acc1.y += v1.y * d1; acc1.z += v1.z * d1; acc1.w += v1.w * d1;
        acc0.x += v2.x * d2; acc0.y += v2.y * d2; acc0.z += v2.z * d2; acc0.w += v2.w * d2;
        acc1.x += v3.x * d3; acc1.y += v3.y * d3; acc1.z += v3.z * d3; acc1.w += v3.w * d3;
    }
    for (; e < end; e++) {
        int s0 = g_csrc[e];
        float d0 = g_dis[s0];
        float4 v0 = *(const float4*)&h[(size_t)s0 * 128 + lane * 4];
        acc0.x += v0.x * d0; acc0.y += v0.y * d0; acc0.z += v0.z * d0; acc0.w += v0.w * d0;
    }

    float4 b = *(const float4*)&bias[lane * 4];
    float4 r;
    r.x = (acc0.x + acc1.x) * dd + b.x;
    r.y = (acc0.y + acc1.y) * dd + b.y;
    r.z = (acc0.z + acc1.z) * dd + b.z;
    r.w = (acc0.w + acc1.w) * dd + b.w;
    if (do_relu) {
        r.x = fmaxf(r.x, 0.f); r.y = fmaxf(r.y, 0.f);
        r.z = fmaxf(r.z, 0.f); r.w = fmaxf(r.w, 0.f);
    }
    *(float4*)&out[(size_t)node * 128 + lane * 4] = r;
}

// ---------------- fused CSR gather (F=40) + bias + log-softmax ---------------
__global__ __launch_bounds__(256) void gather40_softmax_kernel(
    const float* __restrict__ h, const float* __restrict__ bias,
    float* __restrict__ out)
{
    int warp = threadIdx.x >> 5;
    int lane = threadIdx.x & 31;
    int node = blockIdx.x * 8 + warp;
    if (node >= N_NODES) return;

    float dd = g_dis[node];
    const float* hr = h + (size_t)node * N_CLS;
    float accA = hr[lane] * dd;                                  // f = lane
    float accB = (lane < 8) ? hr[32 + lane] * dd : 0.f;          // f = 32+lane

    int e   = g_rowptr[node];
    int end = g_rowptr[node + 1];
    for (; e + 1 < end; e += 2) {
        int s0 = g_csrc[e];
        int s1 = g_csrc[e + 1];
        float d0 = g_dis[s0];
        float d1 = g_dis[s1];
        const float* h0 = h + (size_t)s0 * N_CLS;
        const float* h1 = h + (size_t)s1 * N_CLS;
        accA += h0[lane] * d0 + h1[lane] * d1;
        if (lane < 8) accB += h0[32 + lane] * d0 + h1[32 + lane] * d1;
    }
    if (e < end) {
        int s0 = g_csrc[e];
        float d0 = g_dis[s0];
        const float* h0 = h + (size_t)s0 * N_CLS;
        accA += h0[lane] * d0;
        if (lane < 8) accB += h0[32 + lane] * d0;
    }

    float a = accA * dd + bias[lane];
    float b = (lane < 8) ? (accB * dd + bias[32 + lane]) : -INFINITY;

    float m = fmaxf(a, b);
#pragma unroll
    for (int off = 16; off > 0; off >>= 1)
        m = fmaxf(m, __shfl_xor_sync(0xFFFFFFFFu, m, off));

    float s = expf(a - m) + ((lane < 8) ? expf(b - m) : 0.f);
#pragma unroll
    for (int off = 16; off > 0; off >>= 1)
        s += __shfl_xor_sync(0xFFFFFFFFu, s, off);

    float lse = m + logf(s);
    out[(size_t)node * N_CLS + lane] = a - lse;
    if (lane < 8) out[(size_t)node * N_CLS + 32 + lane] = b - lse;
}

// ---------------- launch ------------------------------------------------------
extern "C" void kernel_launch(void* const* d_in, const int* in_sizes, int n_in,
                              void* d_out, int out_size) {
    const float* x  = (const float*)d_in[0];
    const int*   ei = (const int*)d_in[1];      // int32 [2][N_EDGES]
    const float* W1 = (const float*)d_in[2];
    const float* b1 = (const float*)d_in[3];
    const float* W2 = (const float*)d_in[4];
    const float* b2 = (const float*)d_in[5];
    const float* W3 = (const float*)d_in[6];
    const float* b3 = (const float*)d_in[7];
    float* out = (float*)d_out;

    float *t_ptr, *x_ptr;
    cudaGetSymbolAddress((void**)&t_ptr, g_t);
    cudaGetSymbolAddress((void**)&x_ptr, g_x);

    // side stream + events for overlapping CSR build with GEMM-1
    // (host-side resources, created once; no device memory allocation)
    static cudaStream_t s2 = nullptr;
    static cudaEvent_t evFork = nullptr, evJoin = nullptr;
    if (s2 == nullptr) {
        cudaStreamCreateWithFlags(&s2, cudaStreamNonBlocking);
        cudaEventCreateWithFlags(&evFork, cudaEventDisableTiming);
        cudaEventCreateWithFlags(&evJoin, cudaEventDisableTiming);
    }

    const int gemmGrid   = (N_NODES + 127) / 128;
    const int gatherGrid = (N_NODES + 7) / 8;

    // ---- fork: CSR build on s2, GEMM-1 on main stream ----
    cudaEventRecord(evFork, 0);
    cudaStreamWaitEvent(s2, evFork, 0);

    zero_deg_kernel<<<(N_NODES + 255) / 256, 256, 0, s2>>>();
    hist_deg_kernel<<<(N_EDGES + 255) / 256, 256, 0, s2>>>(ei);
    scan_kernel<<<1, 1024, 0, s2>>>();
    csr_fill_kernel<<<(N_EDGES + 255) / 256, 256, 0, s2>>>(ei);
    cudaEventRecord(evJoin, s2);

    gemm_tf32_kernel<<<gemmGrid, 256>>>(x, W1, t_ptr, N_NODES, 128);

    // ---- join: gather-1 needs both CSR and GEMM-1 ----
    cudaStreamWaitEvent(0, evJoin, 0);
    gather128_kernel<<<gatherGrid, 256>>>(t_ptr, x_ptr, b1, 1);

    // ---- layer 2 ----
    gemm_tf32_kernel<<<gemmGrid, 256>>>(x_ptr, W2, t_ptr, N_NODES, 128);
    gather128_kernel<<<gatherGrid, 256>>>(t_ptr, x_ptr, b2, 1);

    // ---- layer 3 (40 cols) + fused log-softmax ----
    gemm_tf32_kernel<<<gemmGrid, 256>>>(x_ptr, W3, t_ptr, N_NODES, N_CLS);
    gather40_softmax_kernel<<<gatherGrid, 256>>>(t_ptr, b3, out);
}

// round 8
// speedup vs baseline: 3.3994x; 1.0053x over previous
#include <cuda_runtime.h>
#include <stdint.h>
#include <math.h>

#define N_NODES 100000
#define N_EDGES 1600000
#define N_CLS   40

// ---------------- scratch (static device arrays; no cudaMalloc) -------------
__device__ float g_t[(size_t)N_NODES * 128];    // transform output (x @ W)
__device__ float g_x[(size_t)N_NODES * 128];    // layer activation buffer
__device__ int   g_deg[N_NODES];
__device__ float g_dis[N_NODES];                // (deg+1)^{-1/2}
__device__ int   g_rowptr[N_NODES + 1];
__device__ int   g_cursor[N_NODES];
__device__ int   g_csrc[N_EDGES];               // CSR: src ids grouped by dst

// ---------------- degree histogram ------------------------------------------
__global__ void zero_deg_kernel() {
    int i = blockIdx.x * blockDim.x + threadIdx.x;
    if (i < N_NODES) g_deg[i] = 0;
}

__global__ void hist_deg_kernel(const int* __restrict__ ei) {
    int e = blockIdx.x * blockDim.x + threadIdx.x;
    if (e < N_EDGES) atomicAdd(&g_deg[ei[N_EDGES + e]], 1);
}

// ---------------- single-block scan: rowptr, cursor, dis ---------------------
__global__ __launch_bounds__(1024) void scan_kernel() {
    const int T = 1024;
    int tid = threadIdx.x;
    const int per = (N_NODES + T - 1) / T;          // 98
    int start = tid * per;
    int end   = start + per; if (end > N_NODES) end = N_NODES;
    if (start > N_NODES) start = N_NODES;

    int sum = 0;
    for (int i = start; i < end; i++) sum += g_deg[i];

    __shared__ int s[T];
    s[tid] = sum;
    __syncthreads();
    for (int off = 1; off < T; off <<= 1) {
        int v = 0;
        if (tid >= off) v = s[tid - off];
        __syncthreads();
        if (tid >= off) s[tid] += v;
        __syncthreads();
    }
    int run = s[tid] - sum;     // exclusive prefix

    for (int i = start; i < end; i++) {
        int d = g_deg[i];
        g_rowptr[i] = run;
        g_cursor[i] = run;
        g_dis[i] = rsqrtf((float)(d + 1));
        run += d;
    }
    if (end == N_NODES) g_rowptr[N_NODES] = run;
}

__global__ void csr_fill_kernel(const int* __restrict__ ei) {
    int e = blockIdx.x * blockDim.x + threadIdx.x;
    if (e < N_EDGES) {
        int s = ei[e];
        int d = ei[N_EDGES + e];
        int pos = atomicAdd(&g_cursor[d], 1);
        g_csrc[pos] = s;
    }
}

// ---------------- helpers ----------------------------------------------------
__device__ __forceinline__ uint32_t tf32_bits(float x) {
    uint32_t r;
    asm("cvt.rna.tf32.f32 %0, %1;" : "=r"(r) : "f"(x));
    return r;
}

__device__ __forceinline__ void tf32_split(float x, float& hi, float& lo) {
    uint32_t hb = tf32_bits(x);
    float h = __uint_as_float(hb);
    uint32_t lb = tf32_bits(x - h);
    hi = h;
    lo = __uint_as_float(lb);
}

__device__ __forceinline__ void mma_tf32(float* c, uint32_t a0, uint32_t a1,
                                         uint32_t a2, uint32_t a3,
                                         uint32_t b0, uint32_t b1) {
    asm volatile(
        "mma.sync.aligned.m16n8k8.row.col.f32.tf32.tf32.f32 "
        "{%0,%1,%2,%3}, {%4,%5,%6,%7}, {%8,%9}, {%0,%1,%2,%3};"
        : "+f"(c[0]), "+f"(c[1]), "+f"(c[2]), "+f"(c[3])
        : "r"(a0), "r"(a1), "r"(a2), "r"(a3), "r"(b0), "r"(b1));
}

// ---------------- 3xTF32 tensor-core GEMM ------------------------------------
// C[M x Ncols] = A[M x 128] @ W[128 x Ncols].
// Block tile 128x64 (2D grid over N), BK=16, 256 threads, 2 blocks/SM.
// 8 warps in 4m x 2n layout, warp tile 32x32 via m16n8k8.
__global__ __launch_bounds__(256, 2) void gemm_tf32_kernel(
    const float* __restrict__ A, const float* __restrict__ W,
    float* __restrict__ C, int M, int Ncols)
{
    __shared__ float Ah[128][20];
    __shared__ float Al[128][20];
    __shared__ float Bh[16][72];
    __shared__ float Bl[16][72];

    const int tid  = threadIdx.x;
    const int warp = tid >> 5;
    const int lane = tid & 31;
    const int g    = lane >> 2;          // groupID 0..7
    const int tg   = lane & 3;           // tid-in-group 0..3
    const int wm   = (warp >> 1) * 32;   // warp m offset (4 warps in m)
    const int wn   = (warp & 1) * 32;    // warp n offset (2 warps in n)
    const int rowBase = blockIdx.x * 128;
    const int colBase = blockIdx.y * 64;

    // staging addresses: A = 2 float4/thread (128x16), B = 1 float4/thread (16x64)
    const int ar0 = tid >> 2,            akq0 = tid & 3;
    const int ar1 = (tid + 256) >> 2,    akq1 = (tid + 256) & 3;
    const int bk0 = tid >> 4,            bcq0 = tid & 15;

    float acc[2][4][4];
#pragma unroll
    for (int mt = 0; mt < 2; mt++)
#pragma unroll
        for (int nt = 0; nt < 4; nt++)
#pragma unroll
            for (int i = 0; i < 4; i++) acc[mt][nt][i] = 0.f;

    // --- prologue: load tile k0=0 into registers ---
    float4 pa0, pa1, pb0;
    {
        int grow0 = rowBase + ar0, grow1 = rowBase + ar1;
        pa0 = (grow0 < M) ? *(const float4*)&A[(size_t)grow0 * 128 + akq0 * 4]
                          : make_float4(0.f, 0.f, 0.f, 0.f);
        pa1 = (grow1 < M) ? *(const float4*)&A[(size_t)grow1 * 128 + akq1 * 4]
                          : make_float4(0.f, 0.f, 0.f, 0.f);
        int bc = colBase + bcq0 * 4;
        pb0 = (bc + 3 < Ncols) ? *(const float4*)&W[(size_t)bk0 * Ncols + bc]
                               : make_float4(0.f, 0.f, 0.f, 0.f);
    }

    for (int k0 = 0; k0 < 128; k0 += 16) {
        // --- store staged registers to smem with hi/lo split ---
        {
            float4 h, l;
            tf32_split(pa0.x, h.x, l.x); tf32_split(pa0.y, h.y, l.y);
            tf32_split(pa0.z, h.z, l.z); tf32_split(pa0.w, h.w, l.w);
            *(float4*)&Ah[ar0][akq0 * 4] = h;
            *(float4*)&Al[ar0][akq0 * 4] = l;
            tf32_split(pa1.x, h.x, l.x); tf32_split(pa1.y, h.y, l.y);
            tf32_split(pa1.z, h.z, l.z); tf32_split(pa1.w, h.w, l.w);
            *(float4*)&Ah[ar1][akq1 * 4] = h;
            *(float4*)&Al[ar1][akq1 * 4] = l;
            tf32_split(pb0.x, h.x, l.x); tf32_split(pb0.y, h.y, l.y);
            tf32_split(pb0.z, h.z, l.z); tf32_split(pb0.w, h.w, l.w);
            *(float4*)&Bh[bk0][bcq0 * 4] = h;
            *(float4*)&Bl[bk0][bcq0 * 4] = l;
        }
        __syncthreads();

        // --- prefetch next tile's globals (overlaps with mma below) ---
        int kn = k0 + 16;
        if (kn < 128) {
            int grow0 = rowBase + ar0, grow1 = rowBase + ar1;
            pa0 = (grow0 < M) ? *(const float4*)&A[(size_t)grow0 * 128 + kn + akq0 * 4]
                              : make_float4(0.f, 0.f, 0.f, 0.f);
            pa1 = (grow1 < M) ? *(const float4*)&A[(size_t)grow1 * 128 + kn + akq1 * 4]
                              : make_float4(0.f, 0.f, 0.f, 0.f);
            int bc = colBase + bcq0 * 4;
            pb0 = (bc + 3 < Ncols) ? *(const float4*)&W[(size_t)(kn + bk0) * Ncols + bc]
                                   : make_float4(0.f, 0.f, 0.f, 0.f);
        }

        // --- mma: fragments loaded once, reused for all 3 terms ---
#pragma unroll
        for (int kk = 0; kk < 16; kk += 8) {
            uint32_t bh[4][2], bl[4][2];
#pragma unroll
            for (int nt = 0; nt < 4; nt++) {
                int c = wn + nt * 8 + g;
                bh[nt][0] = __float_as_uint(Bh[kk + tg    ][c]);
                bh[nt][1] = __float_as_uint(Bh[kk + tg + 4][c]);
                bl[nt][0] = __float_as_uint(Bl[kk + tg    ][c]);
                bl[nt][1] = __float_as_uint(Bl[kk + tg + 4][c]);
            }
#pragma unroll
            for (int mt = 0; mt < 2; mt++) {
                int r = wm + mt * 16 + g;
                uint32_t ah0 = __float_as_uint(Ah[r    ][kk + tg    ]);
                uint32_t ah1 = __float_as_uint(Ah[r + 8][kk + tg    ]);
                uint32_t ah2 = __float_as_uint(Ah[r    ][kk + tg + 4]);
                uint32_t ah3 = __float_as_uint(Ah[r + 8][kk + tg + 4]);
                uint32_t al0 = __float_as_uint(Al[r    ][kk + tg    ]);
                uint32_t al1 = __float_as_uint(Al[r + 8][kk + tg    ]);
                uint32_t al2 = __float_as_uint(Al[r    ][kk + tg + 4]);
                uint32_t al3 = __float_as_uint(Al[r + 8][kk + tg + 4]);
#pragma unroll
                for (int nt = 0; nt < 4; nt++)
                    mma_tf32(acc[mt][nt], ah0, ah1, ah2, ah3, bh[nt][0], bh[nt][1]);
#pragma unroll
                for (int nt = 0; nt < 4; nt++)
                    mma_tf32(acc[mt][nt], al0, al1, al2, al3, bh[nt][0], bh[nt][1]);
#pragma unroll
                for (int nt = 0; nt < 4; nt++)
                    mma_tf32(acc[mt][nt], ah0, ah1, ah2, ah3, bl[nt][0], bl[nt][1]);
            }
        }
        __syncthreads();
    }

    // --- epilogue ---
#pragma unroll
    for (int mt = 0; mt < 2; mt++) {
#pragma unroll
        for (int nt = 0; nt < 4; nt++) {
            int col = colBase + wn + nt * 8 + 2 * tg;
            if (col >= Ncols) continue;
            int r0 = rowBase + wm + mt * 16 + g;
            int r1 = r0 + 8;
            if (r0 < M)
                *(float2*)&C[(size_t)r0 * Ncols + col] =
                    make_float2(acc[mt][nt][0], acc[mt][nt][1]);
            if (r1 < M)
                *(float2*)&C[(size_t)r1 * Ncols + col] =
                    make_float2(acc[mt][nt][2], acc[mt][nt][3]);
        }
    }
}

// ---------------- fused CSR gather for F=128 ---------------------------------
// out[d] = relu( dis[d] * ( h[d]*dis[d] + sum_{s in N(d)} h[s]*dis[s] ) + b )
__global__ __launch_bounds__(256) void gather128_kernel(
    const float* __restrict__ h, float* __restrict__ out,
    const float* __restrict__ bias, int do_relu)
{
    int warp = threadIdx.x >> 5;
    int lane = threadIdx.x & 31;
    int node = blockIdx.x * 8 + warp;
    if (node >= N_NODES) return;

    float dd = g_dis[node];
    float4 acc0 = *(const float4*)&h[(size_t)node * 128 + lane * 4];
    acc0.x *= dd; acc0.y *= dd; acc0.z *= dd; acc0.w *= dd;
    float4 acc1 = make_float4(0.f, 0.f, 0.f, 0.f);

    int e   = g_rowptr[node];
    int end = g_rowptr[node + 1];

    for (; e + 3 < end; e += 4) {
        int s0 = g_csrc[e];
        int s1 = g_csrc[e + 1];
        int s2 = g_csrc[e + 2];
        int s3 = g_csrc[e + 3];
        float d0 = g_dis[s0], d1 = g_dis[s1], d2 = g_dis[s2], d3 = g_dis[s3];
        float4 v0 = *(const float4*)&h[(size_t)s0 * 128 + lane * 4];
        float4 v1 = *(const float4*)&h[(size_t)s1 * 128 + lane * 4];
        float4 v2 = *(const float4*)&h[(size_t)s2 * 128 + lane * 4];
        float4 v3 = *(const float4*)&h[(size_t)s3 * 128 + lane * 4];
        acc0.x += v0.x * d0; acc0.y += v0.y * d0; acc0.z += v0.z * d0; acc0.w += v0.w * d0;
        acc1.x += v1.x * d1; acc1.y += v1.y * d1; acc1.z += v1.z * d1; acc1.w += v1.w * d1;
        acc0.x += v2.x * d2; acc0.y += v2.y * d2; acc0.z += v2.z * d2; acc0.w += v2.w * d2;
        acc1.x += v3.x * d3; acc1.y += v3.y * d3; acc1.z += v3.z * d3; acc1.w += v3.w * d3;
    }
    for (; e < end; e++) {
        int s0 = g_csrc[e];
        float d0 = g_dis[s0];
        float4 v0 = *(const float4*)&h[(size_t)s0 * 128 + lane * 4];
        acc0.x += v0.x * d0; acc0.y += v0.y * d0; acc0.z += v0.z * d0; acc0.w += v0.w * d0;
    }

    float4 b = *(const float4*)&bias[lane * 4];
    float4 r;
    r.x = (acc0.x + acc1.x) * dd + b.x;
    r.y = (acc0.y + acc1.y) * dd + b.y;
    r.z = (acc0.z + acc1.z) * dd + b.z;
    r.w = (acc0.w + acc1.w) * dd + b.w;
    if (do_relu) {
        r.x = fmaxf(r.x, 0.f); r.y = fmaxf(r.y, 0.f);
        r.z = fmaxf(r.z, 0.f); r.w = fmaxf(r.w, 0.f);
    }
    *(float4*)&out[(size_t)node * 128 + lane * 4] = r;
}

// ---------------- fused CSR gather (F=40) + bias + log-softmax ---------------
__global__ __launch_bounds__(256) void gather40_softmax_kernel(
    const float* __restrict__ h, const float* __restrict__ bias,
    float* __restrict__ out)
{
    int warp = threadIdx.x >> 5;
    int lane = threadIdx.x & 31;
    int node = blockIdx.x * 8 + warp;
    if (node >= N_NODES) return;

    float dd = g_dis[node];
    const float* hr = h + (size_t)node * N_CLS;
    float accA = hr[lane] * dd;                                  // f = lane
    float accB = (lane < 8) ? hr[32 + lane] * dd : 0.f;          // f = 32+lane

    int e   = g_rowptr[node];
    int end = g_rowptr[node + 1];
    for (; e + 1 < end; e += 2) {
        int s0 = g_csrc[e];
        int s1 = g_csrc[e + 1];
        float d0 = g_dis[s0];
        float d1 = g_dis[s1];
        const float* h0 = h + (size_t)s0 * N_CLS;
        const float* h1 = h + (size_t)s1 * N_CLS;
        accA += h0[lane] * d0 + h1[lane] * d1;
        if (lane < 8) accB += h0[32 + lane] * d0 + h1[32 + lane] * d1;
    }
    if (e < end) {
        int s0 = g_csrc[e];
        float d0 = g_dis[s0];
        const float* h0 = h + (size_t)s0 * N_CLS;
        accA += h0[lane] * d0;
        if (lane < 8) accB += h0[32 + lane] * d0;
    }

    float a = accA * dd + bias[lane];
    float b = (lane < 8) ? (accB * dd + bias[32 + lane]) : -INFINITY;

    float m = fmaxf(a, b);
#pragma unroll
    for (int off = 16; off > 0; off >>= 1)
        m = fmaxf(m, __shfl_xor_sync(0xFFFFFFFFu, m, off));

    float s = expf(a - m) + ((lane < 8) ? expf(b - m) : 0.f);
#pragma unroll
    for (int off = 16; off > 0; off >>= 1)
        s += __shfl_xor_sync(0xFFFFFFFFu, s, off);

    float lse = m + logf(s);
    out[(size_t)node * N_CLS + lane] = a - lse;
    if (lane < 8) out[(size_t)node * N_CLS + 32 + lane] = b - lse;
}

// ---------------- launch ------------------------------------------------------
extern "C" void kernel_launch(void* const* d_in, const int* in_sizes, int n_in,
                              void* d_out, int out_size) {
    const float* x  = (const float*)d_in[0];
    const int*   ei = (const int*)d_in[1];      // int32 [2][N_EDGES]
    const float* W1 = (const float*)d_in[2];
    const float* b1 = (const float*)d_in[3];
    const float* W2 = (const float*)d_in[4];
    const float* b2 = (const float*)d_in[5];
    const float* W3 = (const float*)d_in[6];
    const float* b3 = (const float*)d_in[7];
    float* out = (float*)d_out;

    float *t_ptr, *x_ptr;
    cudaGetSymbolAddress((void**)&t_ptr, g_t);
    cudaGetSymbolAddress((void**)&x_ptr, g_x);

    // side stream + events for overlapping CSR build with GEMM-1
    static cudaStream_t s2 = nullptr;
    static cudaEvent_t evFork = nullptr, evJoin = nullptr;
    if (s2 == nullptr) {
        cudaStreamCreateWithFlags(&s2, cudaStreamNonBlocking);
        cudaEventCreateWithFlags(&evFork, cudaEventDisableTiming);
        cudaEventCreateWithFlags(&evJoin, cudaEventDisableTiming);
    }

    const int gemmGridX  = (N_NODES + 127) / 128;
    const dim3 gemmGrid128(gemmGridX, 2);   // 128 cols -> 2 n-blocks
    const dim3 gemmGrid40(gemmGridX, 1);    // 40 cols  -> 1 n-block
    const int gatherGrid = (N_NODES + 7) / 8;

    // ---- fork: CSR build on s2, GEMM-1 on main stream ----
    cudaEventRecord(evFork, 0);
    cudaStreamWaitEvent(s2, evFork, 0);

    zero_deg_kernel<<<(N_NODES + 255) / 256, 256, 0, s2>>>();
    hist_deg_kernel<<<(N_EDGES + 255) / 256, 256, 0, s2>>>(ei);
    scan_kernel<<<1, 1024, 0, s2>>>();
    csr_fill_kernel<<<(N_EDGES + 255) / 256, 256, 0, s2>>>(ei);
    cudaEventRecord(evJoin, s2);

    gemm_tf32_kernel<<<gemmGrid128, 256>>>(x, W1, t_ptr, N_NODES, 128);

    // ---- join: gather-1 needs both CSR and GEMM-1 ----
    cudaStreamWaitEvent(0, evJoin, 0);
    gather128_kernel<<<gatherGrid, 256>>>(t_ptr, x_ptr, b1, 1);

    // ---- layer 2 ----
    gemm_tf32_kernel<<<gemmGrid128, 256>>>(x_ptr, W2, t_ptr, N_NODES, 128);
    gather128_kernel<<<gatherGrid, 256>>>(t_ptr, x_ptr, b2, 1);

    // ---- layer 3 (40 cols) + fused log-softmax ----
    gemm_tf32_kernel<<<gemmGrid40, 256>>>(x_ptr, W3, t_ptr, N_NODES, N_CLS);
    gather40_softmax_kernel<<<gatherGrid, 256>>>(t_ptr, b3, out);
}

// round 10
// speedup vs baseline: 3.6218x; 1.0654x over previous
#include <cuda_runtime.h>
#include <cuda_fp16.h>
#include <stdint.h>
#include <math.h>

#define N_NODES 100000
#define N_EDGES 1600000
#define N_CLS   40

// ---------------- scratch (static device arrays; no cudaMalloc) -------------
__device__ __half g_t[(size_t)N_NODES * 128];   // transform output (x @ W), fp16
__device__ float  g_x[(size_t)N_NODES * 128];   // layer activation buffer, fp32
__device__ int    g_deg[N_NODES];
__device__ float  g_dis[N_NODES];               // (deg+1)^{-1/2}
__device__ int    g_rowptr[N_NODES + 1];
__device__ int    g_cursor[N_NODES];
__device__ int    g_csrc[N_EDGES];              // CSR: src ids grouped by dst

// ---------------- degree histogram ------------------------------------------
__global__ void zero_deg_kernel() {
    int i = blockIdx.x * blockDim.x + threadIdx.x;
    if (i < N_NODES) g_deg[i] = 0;
}

__global__ void hist_deg_kernel(const int* __restrict__ ei) {
    int e = blockIdx.x * blockDim.x + threadIdx.x;
    if (e < N_EDGES) atomicAdd(&g_deg[ei[N_EDGES + e]], 1);
}

// ---------------- single-block scan: rowptr, cursor, dis ---------------------
__global__ __launch_bounds__(1024) void scan_kernel() {
    const int T = 1024;
    int tid = threadIdx.x;
    const int per = (N_NODES + T - 1) / T;          // 98
    int start = tid * per;
    int end   = start + per; if (end > N_NODES) end = N_NODES;
    if (start > N_NODES) start = N_NODES;

    int sum = 0;
    for (int i = start; i < end; i++) sum += g_deg[i];

    __shared__ int s[T];
    s[tid] = sum;
    __syncthreads();
    for (int off = 1; off < T; off <<= 1) {
        int v = 0;
        if (tid >= off) v = s[tid - off];
        __syncthreads();
        if (tid >= off) s[tid] += v;
        __syncthreads();
    }
    int run = s[tid] - sum;     // exclusive prefix

    for (int i = start; i < end; i++) {
        int d = g_deg[i];
        g_rowptr[i] = run;
        g_cursor[i] = run;
        g_dis[i] = rsqrtf((float)(d + 1));
        run += d;
    }
    if (end == N_NODES) g_rowptr[N_NODES] = run;
}

__global__ void csr_fill_kernel(const int* __restrict__ ei) {
    int e = blockIdx.x * blockDim.x + threadIdx.x;
    if (e < N_EDGES) {
        int s = ei[e];
        int d = ei[N_EDGES + e];
        int pos = atomicAdd(&g_cursor[d], 1);
        g_csrc[pos] = s;
    }
}

// ---------------- helpers ----------------------------------------------------
__device__ __forceinline__ uint32_t tf32_bits(float x) {
    uint32_t r;
    asm("cvt.rna.tf32.f32 %0, %1;" : "=r"(r) : "f"(x));
    return r;
}

__device__ __forceinline__ void tf32_split(float x, float& hi, float& lo) {
    uint32_t hb = tf32_bits(x);
    float h = __uint_as_float(hb);
    uint32_t lb = tf32_bits(x - h);
    hi = h;
    lo = __uint_as_float(lb);
}

__device__ __forceinline__ void mma_tf32(float* c, uint32_t a0, uint32_t a1,
                                         uint32_t a2, uint32_t a3,
                                         uint32_t b0, uint32_t b1) {
    asm volatile(
        "mma.sync.aligned.m16n8k8.row.col.f32.tf32.tf32.f32 "
        "{%0,%1,%2,%3}, {%4,%5,%6,%7}, {%8,%9}, {%0,%1,%2,%3};"
        : "+f"(c[0]), "+f"(c[1]), "+f"(c[2]), "+f"(c[3])
        : "r"(a0), "r"(a1), "r"(a2), "r"(a3), "r"(b0), "r"(b1));
}

// ---------------- 3xTF32 tensor-core GEMM, fp16 output -----------------------
// C[M x Ncols] (fp16) = A[M x 128] (fp32) @ W[128 x Ncols] (fp32).
// Block tile 128x64 (2D grid over N), BK=16, 256 threads, 2 blocks/SM.
// 8 warps in 4m x 2n layout, warp tile 32x32 via m16n8k8.
__global__ __launch_bounds__(256, 2) void gemm_tf32_kernel(
    const float* __restrict__ A, const float* __restrict__ W,
    __half* __restrict__ C, int M, int Ncols)
{
    __shared__ float Ah[128][20];
    __shared__ float Al[128][20];
    __shared__ float Bh[16][72];
    __shared__ float Bl[16][72];

    const int tid  = threadIdx.x;
    const int warp = tid >> 5;
    const int lane = tid & 31;
    const int g    = lane >> 2;          // groupID 0..7
    const int tg   = lane & 3;           // tid-in-group 0..3
    const int wm   = (warp >> 1) * 32;   // warp m offset (4 warps in m)
    const int wn   = (warp & 1) * 32;    // warp n offset (2 warps in n)
    const int rowBase = blockIdx.x * 128;
    const int colBase = blockIdx.y * 64;

    const int ar0 = tid >> 2,            akq0 = tid & 3;
    const int ar1 = (tid + 256) >> 2,    akq1 = (tid + 256) & 3;
    const int bk0 = tid >> 4,            bcq0 = tid & 15;

    float acc[2][4][4];
#pragma unroll
    for (int mt = 0; mt < 2; mt++)
#pragma unroll
        for (int nt = 0; nt < 4; nt++)
#pragma unroll
            for (int i = 0; i < 4; i++) acc[mt][nt][i] = 0.f;

    float4 pa0, pa1, pb0;
    {
        int grow0 = rowBase + ar0, grow1 = rowBase + ar1;
        pa0 = (grow0 < M) ? *(const float4*)&A[(size_t)grow0 * 128 + akq0 * 4]
                          : make_float4(0.f, 0.f, 0.f, 0.f);
        pa1 = (grow1 < M) ? *(const float4*)&A[(size_t)grow1 * 128 + akq1 * 4]
                          : make_float4(0.f, 0.f, 0.f, 0.f);
        int bc = colBase + bcq0 * 4;
        pb0 = (bc + 3 < Ncols) ? *(const float4*)&W[(size_t)bk0 * Ncols + bc]
                               : make_float4(0.f, 0.f, 0.f, 0.f);
    }

    for (int k0 = 0; k0 < 128; k0 += 16) {
        {
            float4 h, l;
            tf32_split(pa0.x, h.x, l.x); tf32_split(pa0.y, h.y, l.y);
            tf32_split(pa0.z, h.z, l.z); tf32_split(pa0.w, h.w, l.w);
            *(float4*)&Ah[ar0][akq0 * 4] = h;
            *(float4*)&Al[ar0][akq0 * 4] = l;
            tf32_split(pa1.x, h.x, l.x); tf32_split(pa1.y, h.y, l.y);
            tf32_split(pa1.z, h.z, l.z); tf32_split(pa1.w, h.w, l.w);
            *(float4*)&Ah[ar1][akq1 * 4] = h;
            *(float4*)&Al[ar1][akq1 * 4] = l;
            tf32_split(pb0.x, h.x, l.x); tf32_split(pb0.y, h.y, l.y);
            tf32_split(pb0.z, h.z, l.z); tf32_split(pb0.w, h.w, l.w);
            *(float4*)&Bh[bk0][bcq0 * 4] = h;
            *(float4*)&Bl[bk0][bcq0 * 4] = l;
        }
        __syncthreads();

        int kn = k0 + 16;
        if (kn < 128) {
            int grow0 = rowBase + ar0, grow1 = rowBase + ar1;
            pa0 = (grow0 < M) ? *(const float4*)&A[(size_t)grow0 * 128 + kn + akq0 * 4]
                              : make_float4(0.f, 0.f, 0.f, 0.f);
            pa1 = (grow1 < M) ? *(const float4*)&A[(size_t)grow1 * 128 + kn + akq1 * 4]
                              : make_float4(0.f, 0.f, 0.f, 0.f);
            int bc = colBase + bcq0 * 4;
            pb0 = (bc + 3 < Ncols) ? *(const float4*)&W[(size_t)(kn + bk0) * Ncols + bc]
                                   : make_float4(0.f, 0.f, 0.f, 0.f);
        }

#pragma unroll
        for (int kk = 0; kk < 16; kk += 8) {
            uint32_t bh[4][2], bl[4][2];
#pragma unroll
            for (int nt = 0; nt < 4; nt++) {
                int c = wn + nt * 8 + g;
                bh[nt][0] = __float_as_uint(Bh[kk + tg    ][c]);
                bh[nt][1] = __float_as_uint(Bh[kk + tg + 4][c]);
                bl[nt][0] = __float_as_uint(Bl[kk + tg    ][c]);
                bl[nt][1] = __float_as_uint(Bl[kk + tg + 4][c]);
            }
#pragma unroll
            for (int mt = 0; mt < 2; mt++) {
                int r = wm + mt * 16 + g;
                uint32_t ah0 = __float_as_uint(Ah[r    ][kk + tg    ]);
                uint32_t ah1 = __float_as_uint(Ah[r + 8][kk + tg    ]);
                uint32_t ah2 = __float_as_uint(Ah[r    ][kk + tg + 4]);
                uint32_t ah3 = __float_as_uint(Ah[r + 8][kk + tg + 4]);
                uint32_t al0 = __float_as_uint(Al[r    ][kk + tg    ]);
                uint32_t al1 = __float_as_uint(Al[r + 8][kk + tg    ]);
                uint32_t al2 = __float_as_uint(Al[r    ][kk + tg + 4]);
                uint32_t al3 = __float_as_uint(Al[r + 8][kk + tg + 4]);
#pragma unroll
                for (int nt = 0; nt < 4; nt++)
                    mma_tf32(acc[mt][nt], ah0, ah1, ah2, ah3, bh[nt][0], bh[nt][1]);
#pragma unroll
                for (int nt = 0; nt < 4; nt++)
                    mma_tf32(acc[mt][nt], al0, al1, al2, al3, bh[nt][0], bh[nt][1]);
#pragma unroll
                for (int nt = 0; nt < 4; nt++)
                    mma_tf32(acc[mt][nt], ah0, ah1, ah2, ah3, bl[nt][0], bl[nt][1]);
            }
        }
        __syncthreads();
    }

    // --- epilogue: convert to fp16, store half2 ---
#pragma unroll
    for (int mt = 0; mt < 2; mt++) {
#pragma unroll
        for (int nt = 0; nt < 4; nt++) {
            int col = colBase + wn + nt * 8 + 2 * tg;
            if (col >= Ncols) continue;
            int r0 = rowBase + wm + mt * 16 + g;
            int r1 = r0 + 8;
            if (r0 < M)
                *(__half2*)&C[(size_t)r0 * Ncols + col] =
                    __floats2half2_rn(acc[mt][nt][0], acc[mt][nt][1]);
            if (r1 < M)
                *(__half2*)&C[(size_t)r1 * Ncols + col] =
                    __floats2half2_rn(acc[mt][nt][2], acc[mt][nt][3]);
        }
    }
}

// ---------------- fused CSR gather for F=128 (fp16 input) --------------------
// out[d] = relu( dis[d] * ( h[d]*dis[d] + sum_{s in N(d)} h[s]*dis[s] ) + b )
__global__ __launch_bounds__(256) void gather128_kernel(
    const __half* __restrict__ h, float* __restrict__ out,
    const float* __restrict__ bias, int do_relu)
{
    int warp = threadIdx.x >> 5;
    int lane = threadIdx.x & 31;
    int node = blockIdx.x * 8 + warp;
    if (node >= N_NODES) return;

    float dd = g_dis[node];
    float4 acc0, acc1;
    {
        uint2 u = *(const uint2*)(h + (size_t)node * 128 + lane * 4);
        float2 f01 = __half22float2(*(__half2*)&u.x);
        float2 f23 = __half22float2(*(__half2*)&u.y);
        acc0 = make_float4(f01.x * dd, f01.y * dd, f23.x * dd, f23.y * dd);
        acc1 = make_float4(0.f, 0.f, 0.f, 0.f);
    }

    int e   = g_rowptr[node];
    int end = g_rowptr[node + 1];

    for (; e + 3 < end; e += 4) {
        int s0 = g_csrc[e];
        int s1 = g_csrc[e + 1];
        int s2 = g_csrc[e + 2];
        int s3 = g_csrc[e + 3];
        float d0 = g_dis[s0], d1 = g_dis[s1], d2 = g_dis[s2], d3 = g_dis[s3];
        uint2 u0 = *(const uint2*)(h + (size_t)s0 * 128 + lane * 4);
        uint2 u1 = *(const uint2*)(h + (size_t)s1 * 128 + lane * 4);
        uint2 u2 = *(const uint2*)(h + (size_t)s2 * 128 + lane * 4);
        uint2 u3 = *(const uint2*)(h + (size_t)s3 * 128 + lane * 4);
        float2 a01 = __half22float2(*(__half2*)&u0.x), a23 = __half22float2(*(__half2*)&u0.y);
        float2 b01 = __half22float2(*(__half2*)&u1.x), b23 = __half22float2(*(__half2*)&u1.y);
        float2 c01 = __half22float2(*(__half2*)&u2.x), c23 = __half22float2(*(__half2*)&u2.y);
        float2 e01 = __half22float2(*(__half2*)&u3.x), e23 = __half22float2(*(__half2*)&u3.y);
        acc0.x += a01.x * d0; acc0.y += a01.y * d0; acc0.z += a23.x * d0; acc0.w += a23.y * d0;
        acc1.x += b01.x * d1; acc1.y += b01.y * d1; acc1.z += b23.x * d1; acc1.w += b23.y * d1;
        acc0.x += c01.x * d2; acc0.y += c01.y * d2; acc0.z += c23.x * d2; acc0.w += c23.y * d2;
        acc1.x += e01.x * d3; acc1.y += e01.y * d3; acc1.z += e23.x * d3; acc1.w += e23.y * d3;
    }
    for (; e < end; e++) {
        int s0 = g_csrc[e];
        float d0 = g_dis[s0];
        uint2 u0 = *(const uint2*)(h + (size_t)s0 * 128 + lane * 4);
        float2 a01 = __half22float2(*(__half2*)&u0.x), a23 = __half22float2(*(__half2*)&u0.y);
        acc0.x += a01.x * d0; acc0.y += a01.y * d0; acc0.z += a23.x * d0; acc0.w += a23.y * d0;
    }

    float4 b = *(const float4*)&bias[lane * 4];
    float4 r;
    r.x = (acc0.x + acc1.x) * dd + b.x;
    r.y = (acc0.y + acc1.y) * dd + b.y;
    r.z = (acc0.z + acc1.z) * dd + b.z;
    r.w = (acc0.w + acc1.w) * dd + b.w;
    if (do_relu) {
        r.x = fmaxf(r.x, 0.f); r.y = fmaxf(r.y, 0.f);
        r.z = fmaxf(r.z, 0.f); r.w = fmaxf(r.w, 0.f);
    }
    *(float4*)&out[(size_t)node * 128 + lane * 4] = r;
}

// ------- fused CSR gather (F=40, fp16 in) + bias + log-softmax ---------------
// lanes 0..19 each own classes {2*lane, 2*lane+1}
__global__ __launch_bounds__(256) void gather40_softmax_kernel(
    const __half* __restrict__ h, const float* __restrict__ bias,
    float* __restrict__ out)
{
    int warp = threadIdx.x >> 5;
    int lane = threadIdx.x & 31;
    int node = blockIdx.x * 8 + warp;
    if (node >= N_NODES) return;

    const bool act = (lane < 20);
    float dd = g_dis[node];
    float accA = 0.f, accB = 0.f;
    if (act) {
        __half2 v = *(const __half2*)(h + (size_t)node * N_CLS + lane * 2);
        float2 f = __half22float2(v);
        accA = f.x * dd; accB = f.y * dd;
    }

    int e   = g_rowptr[node];
    int end = g_rowptr[node + 1];
    for (; e + 1 < end; e += 2) {
        int s0 = g_csrc[e];
        int s1 = g_csrc[e + 1];
        float d0 = g_dis[s0];
        float d1 = g_dis[s1];
        if (act) {
            float2 f0 = __half22float2(*(const __half2*)(h + (size_t)s0 * N_CLS + lane * 2));
            float2 f1 = __half22float2(*(const __half2*)(h + (size_t)s1 * N_CLS + lane * 2));
            accA += f0.x * d0 + f1.x * d1;
            accB += f0.y * d0 + f1.y * d1;
        }
    }
    if (e < end) {
        int s0 = g_csrc[e];
        float d0 = g_dis[s0];
        if (act) {
            float2 f0 = __half22float2(*(const __half2*)(h + (size_t)s0 * N_CLS + lane * 2));
            accA += f0.x * d0;
            accB += f0.y * d0;
        }
    }

    float a = act ? (accA * dd + bias[lane * 2])     : -INFINITY;
    float b = act ? (accB * dd + bias[lane * 2 + 1]) : -INFINITY;

    float m = fmaxf(a, b);
#pragma unroll
    for (int off = 16; off > 0; off >>= 1)
        m = fmaxf(m, __shfl_xor_sync(0xFFFFFFFFu, m, off));

    float s = act ? (expf(a - m) + expf(b - m)) : 0.f;
#pragma unroll
    for (int off = 16; off > 0; off >>= 1)
        s += __shfl_xor_sync(0xFFFFFFFFu, s, off);

    float lse = m + logf(s);
    if (act) {
        float2 r = make_float2(a - lse, b - lse);
        *(float2*)&out[(size_t)node * N_CLS + lane * 2] = r;
    }
}

// ---------------- launch ------------------------------------------------------
extern "C" void kernel_launch(void* const* d_in, const int* in_sizes, int n_in,
                              void* d_out, int out_size) {
    const float* x  = (const float*)d_in[0];
    const int*   ei = (const int*)d_in[1];      // int32 [2][N_EDGES]
    const float* W1 = (const float*)d_in[2];
    const float* b1 = (const float*)d_in[3];
    const float* W2 = (const float*)d_in[4];
    const float* b2 = (const float*)d_in[5];
    const float* W3 = (const float*)d_in[6];
    const float* b3 = (const float*)d_in[7];
    float* out = (float*)d_out;

    __half* t_ptr;
    float*  x_ptr;
    cudaGetSymbolAddress((void**)&t_ptr, g_t);
    cudaGetSymbolAddress((void**)&x_ptr, g_x);

    static cudaStream_t s2 = nullptr;
    static cudaEvent_t evFork = nullptr, evJoin = nullptr;
    if (s2 == nullptr) {
        cudaStreamCreateWithFlags(&s2, cudaStreamNonBlocking);
        cudaEventCreateWithFlags(&evFork, cudaEventDisableTiming);
        cudaEventCreateWithFlags(&evJoin, cudaEventDisableTiming);
    }

    const int gemmGridX  = (N_NODES + 127) / 128;
    const dim3 gemmGrid128(gemmGridX, 2);   // 128 cols -> 2 n-blocks
    const dim3 gemmGrid40(gemmGridX, 1);    // 40 cols  -> 1 n-block
    const int gatherGrid = (N_NODES + 7) / 8;

    // ---- fork: CSR build on s2 (zero/hist/scan first), gemm1 at capture idx 3 ----
    cudaEventRecord(evFork, 0);
    cudaStreamWaitEvent(s2, evFork, 0);

    zero_deg_kernel<<<(N_NODES + 255) / 256, 256, 0, s2>>>();   // idx 0
    hist_deg_kernel<<<(N_EDGES + 255) / 256, 256, 0, s2>>>(ei); // idx 1
    scan_kernel<<<1, 1024, 0, s2>>>();                           // idx 2

    gemm_tf32_kernel<<<gemmGrid128, 256>>>(x, W1, t_ptr, N_NODES, 128); // idx 3 (profiled)

    csr_fill_kernel<<<(N_EDGES + 255) / 256, 256, 0, s2>>>(ei); // idx 4
    cudaEventRecord(evJoin, s2);

    // ---- join: gather-1 needs both CSR and GEMM-1 ----
    cudaStreamWaitEvent(0, evJoin, 0);
    gather128_kernel<<<gatherGrid, 256>>>(t_ptr, x_ptr, b1, 1);

    // ---- layer 2 ----
    gemm_tf32_kernel<<<gemmGrid128, 256>>>(x_ptr, W2, t_ptr, N_NODES, 128);
    gather128_kernel<<<gatherGrid, 256>>>(t_ptr, x_ptr, b2, 1);

    // ---- layer 3 (40 cols) + fused log-softmax ----
    gemm_tf32_kernel<<<gemmGrid40, 256>>>(x_ptr, W3, t_ptr, N_NODES, N_CLS);
    gather40_softmax_kernel<<<gatherGrid, 256>>>(t_ptr, b3, out);
}

// round 11
// speedup vs baseline: 3.7913x; 1.0468x over previous
#include <cuda_runtime.h>
#include <cuda_fp16.h>
#include <stdint.h>
#include <math.h>

#define N_NODES 100000
#define N_EDGES 1600000
#define N_CLS   40

// ---------------- scratch (static device arrays; no cudaMalloc) -------------
__device__ __half g_t[(size_t)N_NODES * 128];   // transform output (x @ W), fp16
__device__ float  g_x[(size_t)N_NODES * 128];   // layer activation buffer, fp32
__device__ int    g_deg[N_NODES];
__device__ float  g_dis[N_NODES];               // (deg+1)^{-1/2}
__device__ int    g_rowptr[N_NODES + 1];
__device__ int    g_cursor[N_NODES];
__device__ int    g_csrc[N_EDGES];              // CSR: src ids grouped by dst

// ---------------- degree histogram ------------------------------------------
__global__ void zero_deg_kernel() {
    int i = blockIdx.x * blockDim.x + threadIdx.x;
    if (i < N_NODES) g_deg[i] = 0;
}

__global__ void hist_deg_kernel(const int* __restrict__ ei) {
    int e = blockIdx.x * blockDim.x + threadIdx.x;
    if (e < N_EDGES) atomicAdd(&g_deg[ei[N_EDGES + e]], 1);
}

// ---------------- single-block scan: rowptr, cursor, dis ---------------------
__global__ __launch_bounds__(1024) void scan_kernel() {
    const int T = 1024;
    int tid = threadIdx.x;
    const int per = (N_NODES + T - 1) / T;          // 98
    int start = tid * per;
    int end   = start + per; if (end > N_NODES) end = N_NODES;
    if (start > N_NODES) start = N_NODES;

    int sum = 0;
    for (int i = start; i < end; i++) sum += g_deg[i];

    __shared__ int s[T];
    s[tid] = sum;
    __syncthreads();
    for (int off = 1; off < T; off <<= 1) {
        int v = 0;
        if (tid >= off) v = s[tid - off];
        __syncthreads();
        if (tid >= off) s[tid] += v;
        __syncthreads();
    }
    int run = s[tid] - sum;     // exclusive prefix

    for (int i = start; i < end; i++) {
        int d = g_deg[i];
        g_rowptr[i] = run;
        g_cursor[i] = run;
        g_dis[i] = rsqrtf((float)(d + 1));
        run += d;
    }
    if (end == N_NODES) g_rowptr[N_NODES] = run;
}

__global__ void csr_fill_kernel(const int* __restrict__ ei) {
    int e = blockIdx.x * blockDim.x + threadIdx.x;
    if (e < N_EDGES) {
        int s = ei[e];
        int d = ei[N_EDGES + e];
        int pos = atomicAdd(&g_cursor[d], 1);
        g_csrc[pos] = s;
    }
}

// ---------------- helpers ----------------------------------------------------
// fp16 hi/lo split: x ~= hi + lo, exact to ~2^-22 relative.
__device__ __forceinline__ void h_split(float x, __half& hi, __half& lo) {
    __half h = __float2half_rn(x);
    hi = h;
    lo = __float2half_rn(x - __half2float(h));
}

__device__ __forceinline__ void mma_f16(float* c, uint32_t a0, uint32_t a1,
                                        uint32_t a2, uint32_t a3,
                                        uint32_t b0, uint32_t b1) {
    asm volatile(
        "mma.sync.aligned.m16n8k16.row.col.f32.f16.f16.f32 "
        "{%0,%1,%2,%3}, {%4,%5,%6,%7}, {%8,%9}, {%0,%1,%2,%3};"
        : "+f"(c[0]), "+f"(c[1]), "+f"(c[2]), "+f"(c[3])
        : "r"(a0), "r"(a1), "r"(a2), "r"(a3), "r"(b0), "r"(b1));
}

// ---------------- 3-term fp16 tensor-core GEMM -------------------------------
// C[M x Ncols] (fp16) = A[M x 128] (fp32) @ W[128 x Ncols] (fp32).
// A,B split to fp16 hi/lo; compute ah*bh + al*bh + ah*bl (al*bl ~2^-22, dropped).
// Block tile 128x64 (2D grid over N), BK=32, 256 threads, 2 blocks/SM.
// 8 warps in 4m x 2n layout, warp tile 32x32 via m16n8k16.
// B staged transposed [n][k] so B-fragment k-pairs are single LDS.32.
__global__ __launch_bounds__(256, 2) void gemm_f16x3_kernel(
    const float* __restrict__ A, const float* __restrict__ W,
    __half* __restrict__ C, int M, int Ncols)
{
    __shared__ __half Ahs[128][40];   // [m][k], stride 40 -> conflict-free frags
    __shared__ __half Als[128][40];
    __shared__ __half Bhs[64][40];    // [n][k]
    __shared__ __half Bls[64][40];

    const int tid  = threadIdx.x;
    const int warp = tid >> 5;
    const int lane = tid & 31;
    const int g    = lane >> 2;          // groupID 0..7
    const int tg   = lane & 3;           // tid-in-group 0..3
    const int wm   = (warp >> 1) * 32;   // warp m offset (4 warps in m)
    const int wn   = (warp & 1) * 32;    // warp n offset (2 warps in n)
    const int rowBase = blockIdx.x * 128;
    const int colBase = blockIdx.y * 64;

    float acc[2][4][4];
#pragma unroll
    for (int mt = 0; mt < 2; mt++)
#pragma unroll
        for (int nt = 0; nt < 4; nt++)
#pragma unroll
            for (int i = 0; i < 4; i++) acc[mt][nt][i] = 0.f;

    // --- prologue: load k-chunk 0 into registers ---
    // A: 128x32 f32 = 1024 float4, 4/thread.  B: 32x64 f32 = 512 float4, 2/thread.
    float4 pa[4], pb[2];
#pragma unroll
    for (int i = 0; i < 4; i++) {
        int f = tid + i * 256;
        int r = f >> 3, kq = f & 7;
        int grow = rowBase + r;
        pa[i] = (grow < M) ? *(const float4*)&A[(size_t)grow * 128 + kq * 4]
                           : make_float4(0.f, 0.f, 0.f, 0.f);
    }
#pragma unroll
    for (int i = 0; i < 2; i++) {
        int f = tid + i * 256;
        int k = f >> 4, cq = f & 15;
        int c0 = colBase + cq * 4;
        pb[i] = (c0 < Ncols) ? *(const float4*)&W[(size_t)k * Ncols + c0]
                             : make_float4(0.f, 0.f, 0.f, 0.f);
    }

    for (int kc = 0; kc < 128; kc += 32) {
        // --- stage to smem with fp16 hi/lo split ---
#pragma unroll
        for (int i = 0; i < 4; i++) {
            int f = tid + i * 256;
            int r = f >> 3, kq = f & 7;
            __half h0, l0, h1, l1, h2, l2, h3, l3;
            h_split(pa[i].x, h0, l0); h_split(pa[i].y, h1, l1);
            h_split(pa[i].z, h2, l2); h_split(pa[i].w, h3, l3);
            *(__half2*)&Ahs[r][kq * 4]     = __halves2half2(h0, h1);
            *(__half2*)&Ahs[r][kq * 4 + 2] = __halves2half2(h2, h3);
            *(__half2*)&Als[r][kq * 4]     = __halves2half2(l0, l1);
            *(__half2*)&Als[r][kq * 4 + 2] = __halves2half2(l2, l3);
        }
#pragma unroll
        for (int i = 0; i < 2; i++) {
            int f = tid + i * 256;
            int k = f >> 4, cq = f & 15;
            __half h, l;
            h_split(pb[i].x, h, l); Bhs[cq * 4    ][k] = h; Bls[cq * 4    ][k] = l;
            h_split(pb[i].y, h, l); Bhs[cq * 4 + 1][k] = h; Bls[cq * 4 + 1][k] = l;
            h_split(pb[i].z, h, l); Bhs[cq * 4 + 2][k] = h; Bls[cq * 4 + 2][k] = l;
            h_split(pb[i].w, h, l); Bhs[cq * 4 + 3][k] = h; Bls[cq * 4 + 3][k] = l;
        }
        __syncthreads();

        // --- prefetch next chunk (overlaps mma) ---
        int kn = kc + 32;
        if (kn < 128) {
#pragma unroll
            for (int i = 0; i < 4; i++) {
                int f = tid + i * 256;
                int r = f >> 3, kq = f & 7;
                int grow = rowBase + r;
                pa[i] = (grow < M) ? *(const float4*)&A[(size_t)grow * 128 + kn + kq * 4]
                                   : make_float4(0.f, 0.f, 0.f, 0.f);
            }
#pragma unroll
            for (int i = 0; i < 2; i++) {
                int f = tid + i * 256;
                int k = f >> 4, cq = f & 15;
                int c0 = colBase + cq * 4;
                pb[i] = (c0 < Ncols) ? *(const float4*)&W[(size_t)(kn + k) * Ncols + c0]
                                     : make_float4(0.f, 0.f, 0.f, 0.f);
            }
        }

        // --- mma: 2 k16 steps per chunk, 3 precision terms ---
#pragma unroll
        for (int ks = 0; ks < 2; ks++) {
            const int ko = ks * 16;
            uint32_t bh[4][2], bl[4][2];
#pragma unroll
            for (int nt = 0; nt < 4; nt++) {
                int n = wn + nt * 8 + g;
                bh[nt][0] = *(const uint32_t*)&Bhs[n][ko + 2 * tg];
                bh[nt][1] = *(const uint32_t*)&Bhs[n][ko + 2 * tg + 8];
                bl[nt][0] = *(const uint32_t*)&Bls[n][ko + 2 * tg];
                bl[nt][1] = *(const uint32_t*)&Bls[n][ko + 2 * tg + 8];
            }
#pragma unroll
            for (int mt = 0; mt < 2; mt++) {
                int r = wm + mt * 16 + g;
                uint32_t a0 = *(const uint32_t*)&Ahs[r    ][ko + 2 * tg];
                uint32_t a1 = *(const uint32_t*)&Ahs[r + 8][ko + 2 * tg];
                uint32_t a2 = *(const uint32_t*)&Ahs[r    ][ko + 2 * tg + 8];
                uint32_t a3 = *(const uint32_t*)&Ahs[r + 8][ko + 2 * tg + 8];
                uint32_t l0 = *(const uint32_t*)&Als[r    ][ko + 2 * tg];
                uint32_t l1 = *(const uint32_t*)&Als[r + 8][ko + 2 * tg];
                uint32_t l2 = *(const uint32_t*)&Als[r    ][ko + 2 * tg + 8];
                uint32_t l3 = *(const uint32_t*)&Als[r + 8][ko + 2 * tg + 8];
#pragma unroll
                for (int nt = 0; nt < 4; nt++)
                    mma_f16(acc[mt][nt], a0, a1, a2, a3, bh[nt][0], bh[nt][1]);
#pragma unroll
                for (int nt = 0; nt < 4; nt++)
                    mma_f16(acc[mt][nt], l0, l1, l2, l3, bh[nt][0], bh[nt][1]);
#pragma unroll
                for (int nt = 0; nt < 4; nt++)
                    mma_f16(acc[mt][nt], a0, a1, a2, a3, bl[nt][0], bl[nt][1]);
            }
        }
        __syncthreads();
    }

    // --- epilogue: convert to fp16, store half2 ---
#pragma unroll
    for (int mt = 0; mt < 2; mt++) {
#pragma unroll
        for (int nt = 0; nt < 4; nt++) {
            int col = colBase + wn + nt * 8 + 2 * tg;
            if (col >= Ncols) continue;
            int r0 = rowBase + wm + mt * 16 + g;
            int r1 = r0 + 8;
            if (r0 < M)
                *(__half2*)&C[(size_t)r0 * Ncols + col] =
                    __floats2half2_rn(acc[mt][nt][0], acc[mt][nt][1]);
            if (r1 < M)
                *(__half2*)&C[(size_t)r1 * Ncols + col] =
                    __floats2half2_rn(acc[mt][nt][2], acc[mt][nt][3]);
        }
    }
}

// ---------------- fused CSR gather for F=128 (fp16 input) --------------------
// out[d] = relu( dis[d] * ( h[d]*dis[d] + sum_{s in N(d)} h[s]*dis[s] ) + b )
__global__ __launch_bounds__(256) void gather128_kernel(
    const __half* __restrict__ h, float* __restrict__ out,
    const float* __restrict__ bias, int do_relu)
{
    int warp = threadIdx.x >> 5;
    int lane = threadIdx.x & 31;
    int node = blockIdx.x * 8 + warp;
    if (node >= N_NODES) return;

    float dd = g_dis[node];
    float4 acc0, acc1;
    {
        uint2 u = *(const uint2*)(h + (size_t)node * 128 + lane * 4);
        float2 f01 = __half22float2(*(__half2*)&u.x);
        float2 f23 = __half22float2(*(__half2*)&u.y);
        acc0 = make_float4(f01.x * dd, f01.y * dd, f23.x * dd, f23.y * dd);
        acc1 = make_float4(0.f, 0.f, 0.f, 0.f);
    }

    int e   = g_rowptr[node];
    int end = g_rowptr[node + 1];

    for (; e + 3 < end; e += 4) {
        int s0 = g_csrc[e];
        int s1 = g_csrc[e + 1];
        int s2 = g_csrc[e + 2];
        int s3 = g_csrc[e + 3];
        float d0 = g_dis[s0], d1 = g_dis[s1], d2 = g_dis[s2], d3 = g_dis[s3];
        uint2 u0 = *(const uint2*)(h + (size_t)s0 * 128 + lane * 4);
        uint2 u1 = *(const uint2*)(h + (size_t)s1 * 128 + lane * 4);
        uint2 u2 = *(const uint2*)(h + (size_t)s2 * 128 + lane * 4);
        uint2 u3 = *(const uint2*)(h + (size_t)s3 * 128 + lane * 4);
        float2 a01 = __half22float2(*(__half2*)&u0.x), a23 = __half22float2(*(__half2*)&u0.y);
        float2 b01 = __half22float2(*(__half2*)&u1.x), b23 = __half22float2(*(__half2*)&u1.y);
        float2 c01 = __half22float2(*(__half2*)&u2.x), c23 = __half22float2(*(__half2*)&u2.y);
        float2 e01 = __half22float2(*(__half2*)&u3.x), e23 = __half22float2(*(__half2*)&u3.y);
        acc0.x += a01.x * d0; acc0.y += a01.y * d0; acc0.z += a23.x * d0; acc0.w += a23.y * d0;
        acc1.x += b01.x * d1; acc1.y += b01.y * d1; acc1.z += b23.x * d1; acc1.w += b23.y * d1;
        acc0.x += c01.x * d2; acc0.y += c01.y * d2; acc0.z += c23.x * d2; acc0.w += c23.y * d2;
        acc1.x += e01.x * d3; acc1.y += e01.y * d3; acc1.z += e23.x * d3; acc1.w += e23.y * d3;
    }
    for (; e < end; e++) {
        int s0 = g_csrc[e];
        float d0 = g_dis[s0];
        uint2 u0 = *(const uint2*)(h + (size_t)s0 * 128 + lane * 4);
        float2 a01 = __half22float2(*(__half2*)&u0.x), a23 = __half22float2(*(__half2*)&u0.y);
        acc0.x += a01.x * d0; acc0.y += a01.y * d0; acc0.z += a23.x * d0; acc0.w += a23.y * d0;
    }

    float4 b = *(const float4*)&bias[lane * 4];
    float4 r;
    r.x = (acc0.x + acc1.x) * dd + b.x;
    r.y = (acc0.y + acc1.y) * dd + b.y;
    r.z = (acc0.z + acc1.z) * dd + b.z;
    r.w = (acc0.w + acc1.w) * dd + b.w;
    if (do_relu) {
        r.x = fmaxf(r.x, 0.f); r.y = fmaxf(r.y, 0.f);
        r.z = fmaxf(r.z, 0.f); r.w = fmaxf(r.w, 0.f);
    }
    *(float4*)&out[(size_t)node * 128 + lane * 4] = r;
}

// ------- fused CSR gather (F=40, fp16 in) + bias + log-softmax ---------------
// lanes 0..19 each own classes {2*lane, 2*lane+1}
__global__ __launch_bounds__(256) void gather40_softmax_kernel(
    const __half* __restrict__ h, const float* __restrict__ bias,
    float* __restrict__ out)
{
    int warp = threadIdx.x >> 5;
    int lane = threadIdx.x & 31;
    int node = blockIdx.x * 8 + warp;
    if (node >= N_NODES) return;

    const bool act = (lane < 20);
    float dd = g_dis[node];
    float accA = 0.f, accB = 0.f;
    if (act) {
        __half2 v = *(const __half2*)(h + (size_t)node * N_CLS + lane * 2);
        float2 f = __half22float2(v);
        accA = f.x * dd; accB = f.y * dd;
    }

    int e   = g_rowptr[node];
    int end = g_rowptr[node + 1];
    for (; e + 1 < end; e += 2) {
        int s0 = g_csrc[e];
        int s1 = g_csrc[e + 1];
        float d0 = g_dis[s0];
        float d1 = g_dis[s1];
        if (act) {
            float2 f0 = __half22float2(*(const __half2*)(h + (size_t)s0 * N_CLS + lane * 2));
            float2 f1 = __half22float2(*(const __half2*)(h + (size_t)s1 * N_CLS + lane * 2));
            accA += f0.x * d0 + f1.x * d1;
            accB += f0.y * d0 + f1.y * d1;
        }
    }
    if (e < end) {
        int s0 = g_csrc[e];
        float d0 = g_dis[s0];
        if (act) {
            float2 f0 = __half22float2(*(const __half2*)(h + (size_t)s0 * N_CLS + lane * 2));
            accA += f0.x * d0;
            accB += f0.y * d0;
        }
    }

    float a = act ? (accA * dd + bias[lane * 2])     : -INFINITY;
    float b = act ? (accB * dd + bias[lane * 2 + 1]) : -INFINITY;

    float m = fmaxf(a, b);
#pragma unroll
    for (int off = 16; off > 0; off >>= 1)
        m = fmaxf(m, __shfl_xor_sync(0xFFFFFFFFu, m, off));

    float s = act ? (expf(a - m) + expf(b - m)) : 0.f;
#pragma unroll
    for (int off = 16; off > 0; off >>= 1)
        s += __shfl_xor_sync(0xFFFFFFFFu, s, off);

    float lse = m + logf(s);
    if (act) {
        float2 r = make_float2(a - lse, b - lse);
        *(float2*)&out[(size_t)node * N_CLS + lane * 2] = r;
    }
}

// ---------------- launch ------------------------------------------------------
extern "C" void kernel_launch(void* const* d_in, const int* in_sizes, int n_in,
                              void* d_out, int out_size) {
    const float* x  = (const float*)d_in[0];
    const int*   ei = (const int*)d_in[1];      // int32 [2][N_EDGES]
    const float* W1 = (const float*)d_in[2];
    const float* b1 = (const float*)d_in[3];
    const float* W2 = (const float*)d_in[4];
    const float* b2 = (const float*)d_in[5];
    const float* W3 = (const float*)d_in[6];
    const float* b3 = (const float*)d_in[7];
    float* out = (float*)d_out;

    __half* t_ptr;
    float*  x_ptr;
    cudaGetSymbolAddress((void**)&t_ptr, g_t);
    cudaGetSymbolAddress((void**)&x_ptr, g_x);

    static cudaStream_t s2 = nullptr;
    static cudaEvent_t evFork = nullptr, evJoin = nullptr;
    if (s2 == nullptr) {
        cudaStreamCreateWithFlags(&s2, cudaStreamNonBlocking);
        cudaEventCreateWithFlags(&evFork, cudaEventDisableTiming);
        cudaEventCreateWithFlags(&evJoin, cudaEventDisableTiming);
    }

    const int gemmGridX  = (N_NODES + 127) / 128;
    const dim3 gemmGrid128(gemmGridX, 2);   // 128 cols -> 2 n-blocks
    const dim3 gemmGrid40(gemmGridX, 1);    // 40 cols  -> 1 n-block
    const int gatherGrid = (N_NODES + 7) / 8;

    // ---- fork: CSR build on s2 (zero/hist/scan first), gemm1 at capture idx 3 ----
    cudaEventRecord(evFork, 0);
    cudaStreamWaitEvent(s2, evFork, 0);

    zero_deg_kernel<<<(N_NODES + 255) / 256, 256, 0, s2>>>();   // idx 0
    hist_deg_kernel<<<(N_EDGES + 255) / 256, 256, 0, s2>>>(ei); // idx 1
    scan_kernel<<<1, 1024, 0, s2>>>();                           // idx 2

    gemm_f16x3_kernel<<<gemmGrid128, 256>>>(x, W1, t_ptr, N_NODES, 128); // idx 3 (profiled)

    csr_fill_kernel<<<(N_EDGES + 255) / 256, 256, 0, s2>>>(ei); // idx 4
    cudaEventRecord(evJoin, s2);

    // ---- join: gather-1 needs both CSR and GEMM-1 ----
    cudaStreamWaitEvent(0, evJoin, 0);
    gather128_kernel<<<gatherGrid, 256>>>(t_ptr, x_ptr, b1, 1);

    // ---- layer 2 ----
    gemm_f16x3_kernel<<<gemmGrid128, 256>>>(x_ptr, W2, t_ptr, N_NODES, 128);
    gather128_kernel<<<gatherGrid, 256>>>(t_ptr, x_ptr, b2, 1);

    // ---- layer 3 (40 cols) + fused log-softmax ----
    gemm_f16x3_kernel<<<gemmGrid40, 256>>>(x_ptr, W3, t_ptr, N_NODES, N_CLS);
    gather40_softmax_kernel<<<gatherGrid, 256>>>(t_ptr, b3, out);
}

// round 12
// speedup vs baseline: 4.1674x; 1.0992x over previous
#include <cuda_runtime.h>
#include <cuda_fp16.h>
#include <stdint.h>
#include <math.h>

#define N_NODES 100000
#define N_EDGES 1600000
#define N_CLS   40

// ---------------- scratch (static device arrays; no cudaMalloc) -------------
__device__ __half g_t[(size_t)N_NODES * 128];   // transform output (x @ W), fp16
__device__ float  g_x[(size_t)N_NODES * 128];   // layer activation buffer, fp32
__device__ int    g_deg[N_NODES];
__device__ float  g_dis[N_NODES];               // (deg+1)^{-1/2}
__device__ int    g_rowptr[N_NODES + 1];
__device__ int    g_cursor[N_NODES];
__device__ int    g_csrc[N_EDGES];              // CSR: src ids grouped by dst

// ---------------- degree histogram ------------------------------------------
__global__ void zero_deg_kernel() {
    int i = blockIdx.x * blockDim.x + threadIdx.x;
    if (i < N_NODES) g_deg[i] = 0;
}

__global__ void hist_deg_kernel(const int* __restrict__ ei) {
    int e = blockIdx.x * blockDim.x + threadIdx.x;
    if (e < N_EDGES) atomicAdd(&g_deg[ei[N_EDGES + e]], 1);
}

// ---------------- single-block scan: rowptr, cursor, dis ---------------------
__global__ __launch_bounds__(1024) void scan_kernel() {
    const int T = 1024;
    int tid = threadIdx.x;
    const int per = (N_NODES + T - 1) / T;          // 98
    int start = tid * per;
    int end   = start + per; if (end > N_NODES) end = N_NODES;
    if (start > N_NODES) start = N_NODES;

    int sum = 0;
    for (int i = start; i < end; i++) sum += g_deg[i];

    __shared__ int s[T];
    s[tid] = sum;
    __syncthreads();
    for (int off = 1; off < T; off <<= 1) {
        int v = 0;
        if (tid >= off) v = s[tid - off];
        __syncthreads();
        if (tid >= off) s[tid] += v;
        __syncthreads();
    }
    int run = s[tid] - sum;     // exclusive prefix

    for (int i = start; i < end; i++) {
        int d = g_deg[i];
        g_rowptr[i] = run;
        g_cursor[i] = run;
        g_dis[i] = rsqrtf((float)(d + 1));
        run += d;
    }
    if (end == N_NODES) g_rowptr[N_NODES] = run;
}

__global__ void csr_fill_kernel(const int* __restrict__ ei) {
    int e = blockIdx.x * blockDim.x + threadIdx.x;
    if (e < N_EDGES) {
        int s = ei[e];
        int d = ei[N_EDGES + e];
        int pos = atomicAdd(&g_cursor[d], 1);
        g_csrc[pos] = s;
    }
}

// ---------------- helpers ----------------------------------------------------
// fp16 hi/lo split: x ~= hi + lo, exact to ~2^-22 relative.
__device__ __forceinline__ void h_split(float x, __half& hi, __half& lo) {
    __half h = __float2half_rn(x);
    hi = h;
    lo = __float2half_rn(x - __half2float(h));
}

__device__ __forceinline__ uint32_t pack_h2(__half a, __half b) {
    __half2 h = __halves2half2(a, b);
    return *(uint32_t*)&h;
}

__device__ __forceinline__ void mma_f16(float* c, uint32_t a0, uint32_t a1,
                                        uint32_t a2, uint32_t a3,
                                        uint32_t b0, uint32_t b1) {
    asm volatile(
        "mma.sync.aligned.m16n8k16.row.col.f32.f16.f16.f32 "
        "{%0,%1,%2,%3}, {%4,%5,%6,%7}, {%8,%9}, {%0,%1,%2,%3};"
        : "+f"(c[0]), "+f"(c[1]), "+f"(c[2]), "+f"(c[3])
        : "r"(a0), "r"(a1), "r"(a2), "r"(a3), "r"(b0), "r"(b1));
}

__device__ __forceinline__ void ldsm_x4(uint32_t& r0, uint32_t& r1,
                                        uint32_t& r2, uint32_t& r3, uint32_t addr) {
    asm volatile("ldmatrix.sync.aligned.m8n8.x4.shared.b16 {%0,%1,%2,%3}, [%4];"
                 : "=r"(r0), "=r"(r1), "=r"(r2), "=r"(r3) : "r"(addr));
}

__device__ __forceinline__ void ldsm_x2t(uint32_t& r0, uint32_t& r1, uint32_t addr) {
    asm volatile("ldmatrix.sync.aligned.m8n8.x2.trans.shared.b16 {%0,%1}, [%2];"
                 : "=r"(r0), "=r"(r1) : "r"(addr));
}

// ---------------- 3-term fp16 tensor-core GEMM (ldmatrix) --------------------
// C[M x Ncols] (fp16) = A[M x 128] (fp32) @ W[128 x Ncols] (fp32).
// hi/lo fp16 split; ah*bh + al*bh + ah*bl.  Block tile 128x64, BK=32,
// 256 threads, 2 blocks/SM, 8 warps 4m x 2n, warp tile 32x32 via m16n8k16.
// A staged [m][k] (stride 40), B staged [k][n] (stride 72); fragments via
// ldmatrix.x4 (A) and ldmatrix.x2.trans (B) -> conflict-free loads AND stores.
__global__ __launch_bounds__(256, 2) void gemm_f16x3_kernel(
    const float* __restrict__ A, const float* __restrict__ W,
    __half* __restrict__ C, int M, int Ncols)
{
    __shared__ __half Ahs[128][40];
    __shared__ __half Als[128][40];
    __shared__ __half Bhs[32][72];
    __shared__ __half Bls[32][72];

    const int tid  = threadIdx.x;
    const int warp = tid >> 5;
    const int lane = tid & 31;
    const int g    = lane >> 2;          // groupID 0..7
    const int tg   = lane & 3;           // tid-in-group 0..3
    const int wm   = (warp >> 1) * 32;   // warp m offset (4 warps in m)
    const int wn   = (warp & 1) * 32;    // warp n offset (2 warps in n)
    const int rowBase = blockIdx.x * 128;
    const int colBase = blockIdx.y * 64;

    // ldmatrix lane-address components
    const int li   = lane & 7;
    const int quad = lane >> 3;                       // 0..3
    const int aRow = li + (quad & 1) * 8;             // row offset within a-tile
    const int aCol = (quad >> 1) * 8;                 // col offset within a-tile
    const int bRow = ((lane >> 3) & 1) * 8 + li;      // row offset within b-tile

    const uint32_t sAh = (uint32_t)__cvta_generic_to_shared(&Ahs[0][0]);
    const uint32_t sAl = (uint32_t)__cvta_generic_to_shared(&Als[0][0]);
    const uint32_t sBh = (uint32_t)__cvta_generic_to_shared(&Bhs[0][0]);
    const uint32_t sBl = (uint32_t)__cvta_generic_to_shared(&Bls[0][0]);

    float acc[2][4][4];
#pragma unroll
    for (int mt = 0; mt < 2; mt++)
#pragma unroll
        for (int nt = 0; nt < 4; nt++)
#pragma unroll
            for (int i = 0; i < 4; i++) acc[mt][nt][i] = 0.f;

    // --- prologue: load k-chunk 0 into registers ---
    float4 pa[4], pb[2];
#pragma unroll
    for (int i = 0; i < 4; i++) {
        int f = tid + i * 256;
        int r = f >> 3, kq = f & 7;
        int grow = rowBase + r;
        pa[i] = (grow < M) ? *(const float4*)&A[(size_t)grow * 128 + kq * 4]
                           : make_float4(0.f, 0.f, 0.f, 0.f);
    }
#pragma unroll
    for (int i = 0; i < 2; i++) {
        int f = tid + i * 256;
        int k = f >> 4, cq = f & 15;
        int c0 = colBase + cq * 4;
        pb[i] = (c0 < Ncols) ? *(const float4*)&W[(size_t)k * Ncols + c0]
                             : make_float4(0.f, 0.f, 0.f, 0.f);
    }

    for (int kc = 0; kc < 128; kc += 32) {
        // --- stage to smem with fp16 hi/lo split (vectorized 8B stores) ---
#pragma unroll
        for (int i = 0; i < 4; i++) {
            int f = tid + i * 256;
            int r = f >> 3, kq = f & 7;
            __half h0, l0, h1, l1, h2, l2, h3, l3;
            h_split(pa[i].x, h0, l0); h_split(pa[i].y, h1, l1);
            h_split(pa[i].z, h2, l2); h_split(pa[i].w, h3, l3);
            *(uint2*)&Ahs[r][kq * 4] = make_uint2(pack_h2(h0, h1), pack_h2(h2, h3));
            *(uint2*)&Als[r][kq * 4] = make_uint2(pack_h2(l0, l1), pack_h2(l2, l3));
        }
#pragma unroll
        for (int i = 0; i < 2; i++) {
            int f = tid + i * 256;
            int k = f >> 4, cq = f & 15;
            __half h0, l0, h1, l1, h2, l2, h3, l3;
            h_split(pb[i].x, h0, l0); h_split(pb[i].y, h1, l1);
            h_split(pb[i].z, h2, l2); h_split(pb[i].w, h3, l3);
            *(uint2*)&Bhs[k][cq * 4] = make_uint2(pack_h2(h0, h1), pack_h2(h2, h3));
            *(uint2*)&Bls[k][cq * 4] = make_uint2(pack_h2(l0, l1), pack_h2(l2, l3));
        }
        __syncthreads();

        // --- prefetch next chunk (overlaps mma) ---
        int kn = kc + 32;
        if (kn < 128) {
#pragma unroll
            for (int i = 0; i < 4; i++) {
                int f = tid + i * 256;
                int r = f >> 3, kq = f & 7;
                int grow = rowBase + r;
                pa[i] = (grow < M) ? *(const float4*)&A[(size_t)grow * 128 + kn + kq * 4]
                                   : make_float4(0.f, 0.f, 0.f, 0.f);
            }
#pragma unroll
            for (int i = 0; i < 2; i++) {
                int f = tid + i * 256;
                int k = f >> 4, cq = f & 15;
                int c0 = colBase + cq * 4;
                pb[i] = (c0 < Ncols) ? *(const float4*)&W[(size_t)(kn + k) * Ncols + c0]
                                     : make_float4(0.f, 0.f, 0.f, 0.f);
            }
        }

        // --- mma: 2 k16 steps per chunk, fragments via ldmatrix ---
#pragma unroll
        for (int ks = 0; ks < 2; ks++) {
            const int ko = ks * 16;

            uint32_t bh[4][2], bl[4][2];
#pragma unroll
            for (int nt = 0; nt < 4; nt++) {
                int n0 = wn + nt * 8;
                uint32_t boff = (uint32_t)(((ko + bRow) * 72 + n0) * 2);
                ldsm_x2t(bh[nt][0], bh[nt][1], sBh + boff);
                ldsm_x2t(bl[nt][0], bl[nt][1], sBl + boff);
            }

#pragma unroll
            for (int mt = 0; mt < 2; mt++) {
                int r0 = wm + mt * 16;
                uint32_t aoff = (uint32_t)(((r0 + aRow) * 40 + ko + aCol) * 2);
                uint32_t a0, a1, a2, a3, l0, l1, l2, l3;
                ldsm_x4(a0, a1, a2, a3, sAh + aoff);
                ldsm_x4(l0, l1, l2, l3, sAl + aoff);
#pragma unroll
                for (int nt = 0; nt < 4; nt++)
                    mma_f16(acc[mt][nt], a0, a1, a2, a3, bh[nt][0], bh[nt][1]);
#pragma unroll
                for (int nt = 0; nt < 4; nt++)
                    mma_f16(acc[mt][nt], l0, l1, l2, l3, bh[nt][0], bh[nt][1]);
#pragma unroll
                for (int nt = 0; nt < 4; nt++)
                    mma_f16(acc[mt][nt], a0, a1, a2, a3, bl[nt][0], bl[nt][1]);
            }
        }
        __syncthreads();
    }

    // --- epilogue: convert to fp16, store half2 ---
#pragma unroll
    for (int mt = 0; mt < 2; mt++) {
#pragma unroll
        for (int nt = 0; nt < 4; nt++) {
            int col = colBase + wn + nt * 8 + 2 * tg;
            if (col >= Ncols) continue;
            int r0 = rowBase + wm + mt * 16 + g;
            int r1 = r0 + 8;
            if (r0 < M)
                *(__half2*)&C[(size_t)r0 * Ncols + col] =
                    __floats2half2_rn(acc[mt][nt][0], acc[mt][nt][1]);
            if (r1 < M)
                *(__half2*)&C[(size_t)r1 * Ncols + col] =
                    __floats2half2_rn(acc[mt][nt][2], acc[mt][nt][3]);
        }
    }
}

// ---------------- fused CSR gather for F=128 (fp16 input) --------------------
// out[d] = relu( dis[d] * ( h[d]*dis[d] + sum_{s in N(d)} h[s]*dis[s] ) + b )
__global__ __launch_bounds__(256) void gather128_kernel(
    const __half* __restrict__ h, float* __restrict__ out,
    const float* __restrict__ bias, int do_relu)
{
    int warp = threadIdx.x >> 5;
    int lane = threadIdx.x & 31;
    int node = blockIdx.x * 8 + warp;
    if (node >= N_NODES) return;

    float dd = g_dis[node];
    float4 acc0, acc1;
    {
        uint2 u = *(const uint2*)(h + (size_t)node * 128 + lane * 4);
        float2 f01 = __half22float2(*(__half2*)&u.x);
        float2 f23 = __half22float2(*(__half2*)&u.y);
        acc0 = make_float4(f01.x * dd, f01.y * dd, f23.x * dd, f23.y * dd);
        acc1 = make_float4(0.f, 0.f, 0.f, 0.f);
    }

    int e   = g_rowptr[node];
    int end = g_rowptr[node + 1];

    for (; e + 3 < end; e += 4) {
        int s0 = g_csrc[e];
        int s1 = g_csrc[e + 1];
        int s2 = g_csrc[e + 2];
        int s3 = g_csrc[e + 3];
        float d0 = g_dis[s0], d1 = g_dis[s1], d2 = g_dis[s2], d3 = g_dis[s3];
        uint2 u0 = *(const uint2*)(h + (size_t)s0 * 128 + lane * 4);
        uint2 u1 = *(const uint2*)(h + (size_t)s1 * 128 + lane * 4);
        uint2 u2 = *(const uint2*)(h + (size_t)s2 * 128 + lane * 4);
        uint2 u3 = *(const uint2*)(h + (size_t)s3 * 128 + lane * 4);
        float2 a01 = __half22float2(*(__half2*)&u0.x), a23 = __half22float2(*(__half2*)&u0.y);
        float2 b01 = __half22float2(*(__half2*)&u1.x), b23 = __half22float2(*(__half2*)&u1.y);
        float2 c01 = __half22float2(*(__half2*)&u2.x), c23 = __half22float2(*(__half2*)&u2.y);
        float2 e01 = __half22float2(*(__half2*)&u3.x), e23 = __half22float2(*(__half2*)&u3.y);
        acc0.x += a01.x * d0; acc0.y += a01.y * d0; acc0.z += a23.x * d0; acc0.w += a23.y * d0;
        acc1.x += b01.x * d1; acc1.y += b01.y * d1; acc1.z += b23.x * d1; acc1.w += b23.y * d1;
        acc0.x += c01.x * d2; acc0.y += c01.y * d2; acc0.z += c23.x * d2; acc0.w += c23.y * d2;
        acc1.x += e01.x * d3; acc1.y += e01.y * d3; acc1.z += e23.x * d3; acc1.w += e23.y * d3;
    }
    for (; e < end; e++) {
        int s0 = g_csrc[e];
        float d0 = g_dis[s0];
        uint2 u0 = *(const uint2*)(h + (size_t)s0 * 128 + lane * 4);
        float2 a01 = __half22float2(*(__half2*)&u0.x), a23 = __half22float2(*(__half2*)&u0.y);
        acc0.x += a01.x * d0; acc0.y += a01.y * d0; acc0.z += a23.x * d0; acc0.w += a23.y * d0;
    }

    float4 b = *(const float4*)&bias[lane * 4];
    float4 r;
    r.x = (acc0.x + acc1.x) * dd + b.x;
    r.y = (acc0.y + acc1.y) * dd + b.y;
    r.z = (acc0.z + acc1.z) * dd + b.z;
    r.w = (acc0.w + acc1.w) * dd + b.w;
    if (do_relu) {
        r.x = fmaxf(r.x, 0.f); r.y = fmaxf(r.y, 0.f);
        r.z = fmaxf(r.z, 0.f); r.w = fmaxf(r.w, 0.f);
    }
    *(float4*)&out[(size_t)node * 128 + lane * 4] = r;
}

// ------- fused CSR gather (F=40, fp16 in) + bias + log-softmax ---------------
// lanes 0..19 each own classes {2*lane, 2*lane+1}
__global__ __launch_bounds__(256) void gather40_softmax_kernel(
    const __half* __restrict__ h, const float* __restrict__ bias,
    float* __restrict__ out)
{
    int warp = threadIdx.x >> 5;
    int lane = threadIdx.x & 31;
    int node = blockIdx.x * 8 + warp;
    if (node >= N_NODES) return;

    const bool act = (lane < 20);
    float dd = g_dis[node];
    float accA = 0.f, accB = 0.f;
    if (act) {
        __half2 v = *(const __half2*)(h + (size_t)node * N_CLS + lane * 2);
        float2 f = __half22float2(v);
        accA = f.x * dd; accB = f.y * dd;
    }

    int e   = g_rowptr[node];
    int end = g_rowptr[node + 1];
    for (; e + 1 < end; e += 2) {
        int s0 = g_csrc[e];
        int s1 = g_csrc[e + 1];
        float d0 = g_dis[s0];
        float d1 = g_dis[s1];
        if (act) {
            float2 f0 = __half22float2(*(const __half2*)(h + (size_t)s0 * N_CLS + lane * 2));
            float2 f1 = __half22float2(*(const __half2*)(h + (size_t)s1 * N_CLS + lane * 2));
            accA += f0.x * d0 + f1.x * d1;
            accB += f0.y * d0 + f1.y * d1;
        }
    }
    if (e < end) {
        int s0 = g_csrc[e];
        float d0 = g_dis[s0];
        if (act) {
            float2 f0 = __half22float2(*(const __half2*)(h + (size_t)s0 * N_CLS + lane * 2));
            accA += f0.x * d0;
            accB += f0.y * d0;
        }
    }

    float a = act ? (accA * dd + bias[lane * 2])     : -INFINITY;
    float b = act ? (accB * dd + bias[lane * 2 + 1]) : -INFINITY;

    float m = fmaxf(a, b);
#pragma unroll
    for (int off = 16; off > 0; off >>= 1)
        m = fmaxf(m, __shfl_xor_sync(0xFFFFFFFFu, m, off));

    float s = act ? (expf(a - m) + expf(b - m)) : 0.f;
#pragma unroll
    for (int off = 16; off > 0; off >>= 1)
        s += __shfl_xor_sync(0xFFFFFFFFu, s, off);

    float lse = m + logf(s);
    if (act) {
        float2 r = make_float2(a - lse, b - lse);
        *(float2*)&out[(size_t)node * N_CLS + lane * 2] = r;
    }
}

// ---------------- launch ------------------------------------------------------
extern "C" void kernel_launch(void* const* d_in, const int* in_sizes, int n_in,
                              void* d_out, int out_size) {
    const float* x  = (const float*)d_in[0];
    const int*   ei = (const int*)d_in[1];      // int32 [2][N_EDGES]
    const float* W1 = (const float*)d_in[2];
    const float* b1 = (const float*)d_in[3];
    const float* W2 = (const float*)d_in[4];
    const float* b2 = (const float*)d_in[5];
    const float* W3 = (const float*)d_in[6];
    const float* b3 = (const float*)d_in[7];
    float* out = (float*)d_out;

    __half* t_ptr;
    float*  x_ptr;
    cudaGetSymbolAddress((void**)&t_ptr, g_t);
    cudaGetSymbolAddress((void**)&x_ptr, g_x);

    static cudaStream_t s2 = nullptr;
    static cudaEvent_t evFork = nullptr, evJoin = nullptr;
    if (s2 == nullptr) {
        cudaStreamCreateWithFlags(&s2, cudaStreamNonBlocking);
        cudaEventCreateWithFlags(&evFork, cudaEventDisableTiming);
        cudaEventCreateWithFlags(&evJoin, cudaEventDisableTiming);
    }

    const int gemmGridX  = (N_NODES + 127) / 128;
    const dim3 gemmGrid128(gemmGridX, 2);   // 128 cols -> 2 n-blocks
    const dim3 gemmGrid40(gemmGridX, 1);    // 40 cols  -> 1 n-block
    const int gatherGrid = (N_NODES + 7) / 8;

    // ---- fork: CSR build on s2 (zero/hist/scan first), gemm1 at capture idx 3 ----
    cudaEventRecord(evFork, 0);
    cudaStreamWaitEvent(s2, evFork, 0);

    zero_deg_kernel<<<(N_NODES + 255) / 256, 256, 0, s2>>>();   // idx 0
    hist_deg_kernel<<<(N_EDGES + 255) / 256, 256, 0, s2>>>(ei); // idx 1
    scan_kernel<<<1, 1024, 0, s2>>>();                           // idx 2

    gemm_f16x3_kernel<<<gemmGrid128, 256>>>(x, W1, t_ptr, N_NODES, 128); // idx 3 (profiled)

    csr_fill_kernel<<<(N_EDGES + 255) / 256, 256, 0, s2>>>(ei); // idx 4
    cudaEventRecord(evJoin, s2);

    // ---- join: gather-1 needs both CSR and GEMM-1 ----
    cudaStreamWaitEvent(0, evJoin, 0);
    gather128_kernel<<<gatherGrid, 256>>>(t_ptr, x_ptr, b1, 1);

    // ---- layer 2 ----
    gemm_f16x3_kernel<<<gemmGrid128, 256>>>(x_ptr, W2, t_ptr, N_NODES, 128);
    gather128_kernel<<<gatherGrid, 256>>>(t_ptr, x_ptr, b2, 1);

    // ---- layer 3 (40 cols) + fused log-softmax ----
    gemm_f16x3_kernel<<<gemmGrid40, 256>>>(x_ptr, W3, t_ptr, N_NODES, N_CLS);
    gather40_softmax_kernel<<<gatherGrid, 256>>>(t_ptr, b3, out);
}